// round 8
// baseline (speedup 1.0000x reference)
#include <cuda_runtime.h>
#include <cuda_bf16.h>
#include <cstdint>
#include <math.h>

// Problem constants
#define BATCH 8
#define NDIM  1024
#define MEDIM 1024
#define DDIM  1024

typedef __nv_bfloat16 bf16;

// ============================================================================
// Scratch (device globals; no allocation allowed)
// ============================================================================
#define EL8M ((size_t)BATCH * 1024 * 1024)
__device__ bf16 g_z1[EL8M], g_z2[EL8M], g_z3[EL8M];                 // z limbs [B,N,D]
__device__ bf16 g_m1[1024*1024], g_m2[1024*1024], g_m3[1024*1024];  // M^T limbs [D,D]
__device__ bf16 g_p1[EL8M], g_p2[EL8M], g_p3[EL8M];                 // zM limbs [B,N,D]
__device__ bf16 g_e1[EL8M], g_e2[EL8M], g_e3[EL8M];                 // e limbs [B,ME,D]
__device__ bf16 g_t1[EL8M], g_t2[EL8M];                             // e^T limbs [B,D,ME]
__device__ bf16 g_a1[EL8M], g_a2[EL8M];                             // A limbs [B,N,ME]
__device__ float g_colsum[BATCH * MEDIM];

// ============================================================================
// PTX helpers (compute_103-safe: mma.sync / ldmatrix / cp.async only)
// ============================================================================
__device__ __forceinline__ uint32_t smem_u32(const void* p) {
    uint32_t a;
    asm("{ .reg .u64 t; cvta.to.shared.u64 t, %1; cvt.u32.u64 %0, t; }" : "=r"(a) : "l"(p));
    return a;
}

#define CP_ASYNC16(dst, src) \
    asm volatile("cp.async.cg.shared.global [%0], [%1], 16;" :: "r"(dst), "l"(src))
#define CP_COMMIT() asm volatile("cp.async.commit_group;" ::: "memory")
#define CP_WAIT2()  asm volatile("cp.async.wait_group 2;" ::: "memory")

#define LDMATRIX_X4(r, addr) \
    asm volatile("ldmatrix.sync.aligned.m8n8.x4.shared.b16 {%0,%1,%2,%3}, [%4];" \
        : "=r"((r)[0]), "=r"((r)[1]), "=r"((r)[2]), "=r"((r)[3]) : "r"(addr))

#define MMA16816(d, a, b0, b1) \
    asm volatile("mma.sync.aligned.m16n8k16.row.col.f32.bf16.bf16.f32 " \
        "{%0,%1,%2,%3}, {%4,%5,%6,%7}, {%8,%9}, {%0,%1,%2,%3};" \
        : "+f"((d)[0]), "+f"((d)[1]), "+f"((d)[2]), "+f"((d)[3]) \
        : "r"((a)[0]), "r"((a)[1]), "r"((a)[2]), "r"((a)[3]), "r"(b0), "r"(b1))

#define SWZ(x) ((x) ^ (((x) >> 3) & 0x70))

// ============================================================================
// Split helpers
// ============================================================================
__device__ __forceinline__ void split3f(float v, bf16& h, bf16& m, bf16& l) {
    h = __float2bfloat16(v);
    float r = v - __bfloat162float(h);
    m = __float2bfloat16(r);
    l = __float2bfloat16(r - __bfloat162float(m));
}
__device__ __forceinline__ void split2f(float v, bf16& h, bf16& l) {
    h = __float2bfloat16(v);
    l = __float2bfloat16(v - __bfloat162float(h));
}

__global__ void split3_kernel(const float* __restrict__ x, bf16* __restrict__ h,
                              bf16* __restrict__ m, bf16* __restrict__ l) {
    size_t i = (size_t)blockIdx.x * blockDim.x + threadIdx.x;
    split3f(x[i], h[i], m[i], l[i]);
}

// transpose + 3-split (single 1024x1024 matrix): out[r][c] = in[c][r]
__global__ void tsplit3_kernel(const float* __restrict__ x, bf16* __restrict__ h,
                               bf16* __restrict__ m, bf16* __restrict__ l) {
    __shared__ float tile[32][33];
    int x0 = blockIdx.x * 32, y0 = blockIdx.y * 32;
    for (int i = threadIdx.y; i < 32; i += 8)
        tile[i][threadIdx.x] = x[(size_t)(y0 + i) * 1024 + x0 + threadIdx.x];
    __syncthreads();
    for (int i = threadIdx.y; i < 32; i += 8) {
        float v = tile[threadIdx.x][i];
        size_t o = (size_t)(x0 + i) * 1024 + y0 + threadIdx.x;
        split3f(v, h[o], m[o], l[o]);
    }
}

// batched transpose + 2-split: out[b][r][c] = in[b][c][r]
__global__ void tsplit2_kernel(const float* __restrict__ x, bf16* __restrict__ h,
                               bf16* __restrict__ l) {
    __shared__ float tile[32][33];
    size_t boff = (size_t)blockIdx.z * 1024 * 1024;
    int x0 = blockIdx.x * 32, y0 = blockIdx.y * 32;
    for (int i = threadIdx.y; i < 32; i += 8)
        tile[i][threadIdx.x] = x[boff + (size_t)(y0 + i) * 1024 + x0 + threadIdx.x];
    __syncthreads();
    for (int i = threadIdx.y; i < 32; i += 8) {
        float v = tile[threadIdx.x][i];
        size_t o = boff + (size_t)(x0 + i) * 1024 + y0 + threadIdx.x;
        split2f(v, h[o], l[o]);
    }
}

// ============================================================================
// bf16 tensor-core GEMM (mma.sync m16n8k16), Ozaki multi-segment K.
// CTA tile 128x256, warp tile 64x64 (8 warps, 2x4), BK=64, 3-stage cp.async.
// C[128x256 tile] = sum_seg A_seg[128,1024] @ B_seg[256,1024]^T
// Both operands K-major bf16. EPI: 0=f32 store, 1=sigmoid f32, 2=3-limb bf16.
// ============================================================================
struct GemmParams {
    const bf16* a[6];
    const bf16* b[6];
    long strideA, strideB, strideC;
    float* C;
    bf16 *oh, *om, *ol;
};

#define STAGE_BYTES 49152u   // A 16KB + B 32KB
#define SMEM_BYTES  147456   // 3 stages

template <int NSEG, int EPI>
__global__ void __launch_bounds__(256, 1) mm_kernel(GemmParams p) {
    extern __shared__ char smem[];
    const uint32_t sb = smem_u32(smem);
    const int tid = threadIdx.x;
    const int lid = tid & 31;
    const int wid = tid >> 5;
    const int wm = wid & 1;    // 0..1 -> 64-row slice
    const int wn = wid >> 1;   // 0..3 -> 64-col slice

    const int b = blockIdx.z;
    const long row0 = (long)blockIdx.y * 128;
    const long col0 = (long)blockIdx.x * 256;

    const int NCH = NSEG * 16;   // K chunks of 64

    float acc[4][8][4];
#pragma unroll
    for (int i = 0; i < 4; i++)
#pragma unroll
        for (int j = 0; j < 8; j++)
#pragma unroll
            for (int k = 0; k < 4; k++) acc[i][j][k] = 0.0f;

    // Per chunk: A 128x64 bf16 = 16KB (1024 x16B), B 256x64 = 32KB (2048 x16B).
    auto load_chunk = [&](int c, int stage) {
        const int seg = c >> 4;
        const long kk = (long)(c & 15) << 6;
        const bf16* Ag = p.a[seg] + (long)b * p.strideA + kk;
        const bf16* Bg = p.b[seg] + (long)b * p.strideB + kk;
        const uint32_t sa = sb + (uint32_t)stage * STAGE_BYTES;
        const uint32_t sbb = sa + 16384u;
#pragma unroll
        for (int t = 0; t < 4; t++) {           // A: 1024 transfers
            int idx = tid + (t << 8);
            int r = idx >> 3;
            int c16 = idx & 7;
            uint32_t bo = (uint32_t)(r << 7) + (uint32_t)(c16 << 4);
            CP_ASYNC16(sa + SWZ(bo), Ag + (row0 + r) * 1024 + (c16 << 3));
        }
#pragma unroll
        for (int t = 0; t < 8; t++) {           // B: 2048 transfers
            int idx = tid + (t << 8);
            int r = idx >> 3;                   // 0..255
            int c16 = idx & 7;
            uint32_t bo = (uint32_t)(r << 7) + (uint32_t)(c16 << 4);
            CP_ASYNC16(sbb + SWZ(bo), Bg + (col0 + r) * 1024 + (c16 << 3));
        }
    };

    load_chunk(0, 0); CP_COMMIT();
    load_chunk(1, 1); CP_COMMIT();

    for (int c = 0; c < NCH; c++) {
        if (c + 2 < NCH) load_chunk(c + 2, (c + 2) % 3);
        CP_COMMIT();
        CP_WAIT2();
        __syncthreads();

        const uint32_t sa  = sb + (uint32_t)(c % 3) * STAGE_BYTES;
        const uint32_t sbb = sa + 16384u;

#pragma unroll
        for (int j = 0; j < 4; j++) {       // k16 step within 64-chunk
            uint32_t af[4][4];
#pragma unroll
            for (int mi = 0; mi < 4; mi++) {
                int row = wm * 64 + mi * 16 + (lid & 15);
                uint32_t bo = (uint32_t)(row << 7) + (uint32_t)(j << 5)
                            + (uint32_t)((lid >> 4) << 4);
                LDMATRIX_X4(af[mi], sa + SWZ(bo));
            }
#pragma unroll
            for (int ni = 0; ni < 4; ni++) {  // 16-col groups
                uint32_t bfr[4];
                int nr = wn * 64 + ni * 16 + (lid & 7) + (((lid >> 4) & 1) << 3);
                uint32_t bo = (uint32_t)(nr << 7) + (uint32_t)(j << 5)
                            + (uint32_t)(((lid >> 3) & 1) << 4);
                LDMATRIX_X4(bfr, sbb + SWZ(bo));
#pragma unroll
                for (int mi = 0; mi < 4; mi++) {
                    MMA16816(acc[mi][ni * 2 + 0], af[mi], bfr[0], bfr[1]);
                    MMA16816(acc[mi][ni * 2 + 1], af[mi], bfr[2], bfr[3]);
                }
            }
        }
        __syncthreads();
    }

    // ---- Epilogue (direct from registers) ----
    const int r_in = lid >> 2;
    const int c_in = (lid & 3) << 1;
#pragma unroll
    for (int mi = 0; mi < 4; mi++) {
        const long row = row0 + wm * 64 + mi * 16 + r_in;
#pragma unroll
        for (int nj = 0; nj < 8; nj++) {
            const long colg = col0 + wn * 64 + nj * 8 + c_in;
            float v0 = acc[mi][nj][0], v1 = acc[mi][nj][1];
            float v2 = acc[mi][nj][2], v3 = acc[mi][nj][3];
            if (EPI == 0 || EPI == 1) {
                if (EPI == 1) {
                    v0 = 1.0f / (1.0f + expf(-v0));
                    v1 = 1.0f / (1.0f + expf(-v1));
                    v2 = 1.0f / (1.0f + expf(-v2));
                    v3 = 1.0f / (1.0f + expf(-v3));
                }
                float* Cp = p.C + (long)b * p.strideC;
                *reinterpret_cast<float2*>(Cp + row * 1024 + colg)       = make_float2(v0, v1);
                *reinterpret_cast<float2*>(Cp + (row + 8) * 1024 + colg) = make_float2(v2, v3);
            } else {
                const long base0 = (long)b * p.strideC + row * 1024 + colg;
                const long base1 = base0 + 8 * 1024;
                bf16 h0, m0, l0, h1, m1, l1;
                split3f(v0, h0, m0, l0); split3f(v1, h1, m1, l1);
                *reinterpret_cast<__nv_bfloat162*>(p.oh + base0) = __nv_bfloat162(h0, h1);
                *reinterpret_cast<__nv_bfloat162*>(p.om + base0) = __nv_bfloat162(m0, m1);
                *reinterpret_cast<__nv_bfloat162*>(p.ol + base0) = __nv_bfloat162(l0, l1);
                split3f(v2, h0, m0, l0); split3f(v3, h1, m1, l1);
                *reinterpret_cast<__nv_bfloat162*>(p.oh + base1) = __nv_bfloat162(h0, h1);
                *reinterpret_cast<__nv_bfloat162*>(p.om + base1) = __nv_bfloat162(m0, m1);
                *reinterpret_cast<__nv_bfloat162*>(p.ol + base1) = __nv_bfloat162(l0, l1);
            }
        }
    }
}

// ============================================================================
// Softmax pieces
// ============================================================================
__global__ void colsum_kernel(const float* __restrict__ S, float* __restrict__ cs) {
    int b = blockIdx.y;
    int m = blockIdx.x * blockDim.x + threadIdx.x;
    const float* p = S + (size_t)b * NDIM * MEDIM + m;
    float s = 0.0f;
#pragma unroll 4
    for (int n = 0; n < NDIM; n++) s += expf(p[(size_t)n * MEDIM]);
    cs[b * MEDIM + m] = s;
}

// A = exp(S)/colsum (in place), plus 2-limb bf16 split of A
__global__ void softmax_split_kernel(float* __restrict__ S, const float* __restrict__ cs,
                                     bf16* __restrict__ ah, bf16* __restrict__ al) {
    size_t g = (size_t)blockIdx.x * blockDim.x + threadIdx.x;
    int b = (int)(g >> 20);
    int m = (int)(g & (MEDIM - 1));
    float v = expf(S[g]) / cs[b * MEDIM + m];
    S[g] = v;
    split2f(v, ah[g], al[g]);
}

// ============================================================================
// Host launch
// ============================================================================
extern "C" void kernel_launch(void* const* d_in, const int* in_sizes, int n_in,
                              void* d_out, int out_size) {
    const float* z = (const float*)d_in[0];
    const float* e = (const float*)d_in[1];
    const float* M = (const float*)d_in[2];

    float* e_out = (float*)d_out;
    float* A_out = (float*)d_out + (size_t)BATCH * NDIM * DDIM;

    bf16 *z1, *z2, *z3, *m1, *m2, *m3, *p1, *p2, *p3, *e1, *e2, *e3, *t1, *t2, *a1, *a2;
    float* cs;
    cudaGetSymbolAddress((void**)&z1, g_z1); cudaGetSymbolAddress((void**)&z2, g_z2);
    cudaGetSymbolAddress((void**)&z3, g_z3);
    cudaGetSymbolAddress((void**)&m1, g_m1); cudaGetSymbolAddress((void**)&m2, g_m2);
    cudaGetSymbolAddress((void**)&m3, g_m3);
    cudaGetSymbolAddress((void**)&p1, g_p1); cudaGetSymbolAddress((void**)&p2, g_p2);
    cudaGetSymbolAddress((void**)&p3, g_p3);
    cudaGetSymbolAddress((void**)&e1, g_e1); cudaGetSymbolAddress((void**)&e2, g_e2);
    cudaGetSymbolAddress((void**)&e3, g_e3);
    cudaGetSymbolAddress((void**)&t1, g_t1); cudaGetSymbolAddress((void**)&t2, g_t2);
    cudaGetSymbolAddress((void**)&a1, g_a1); cudaGetSymbolAddress((void**)&a2, g_a2);
    cudaGetSymbolAddress((void**)&cs, g_colsum);

    cudaFuncSetAttribute(mm_kernel<6, 2>, cudaFuncAttributeMaxDynamicSharedMemorySize, SMEM_BYTES);
    cudaFuncSetAttribute(mm_kernel<6, 1>, cudaFuncAttributeMaxDynamicSharedMemorySize, SMEM_BYTES);
    cudaFuncSetAttribute(mm_kernel<3, 0>, cudaFuncAttributeMaxDynamicSharedMemorySize, SMEM_BYTES);

    const long S8 = (long)1024 * 1024;

    // ---- Prep: limb splits ----
    split3_kernel<<<(BATCH * S8) / 256, 256>>>(z, z1, z2, z3);
    split3_kernel<<<(BATCH * S8) / 256, 256>>>(e, e1, e2, e3);
    tsplit3_kernel<<<dim3(32, 32, 1), dim3(32, 8)>>>(M, m1, m2, m3);
    tsplit2_kernel<<<dim3(32, 32, BATCH), dim3(32, 8)>>>(e, t1, t2);

    dim3 gg(4, 8, BATCH);   // cols/256, rows/128, batch
    dim3 gb(256);

    // ---- GEMM1: zM = z @ M  (limb pairs hh,hm,mh,hl,mm,lh) -> zM limbs ----
    {
        GemmParams p{};
        p.a[0] = z1; p.a[1] = z1; p.a[2] = z2; p.a[3] = z1; p.a[4] = z2; p.a[5] = z3;
        p.b[0] = m1; p.b[1] = m2; p.b[2] = m1; p.b[3] = m3; p.b[4] = m2; p.b[5] = m1;
        p.strideA = S8; p.strideB = 0; p.strideC = S8;
        p.oh = p1; p.om = p2; p.ol = p3; p.C = nullptr;
        mm_kernel<6, 2><<<gg, gb, SMEM_BYTES>>>(p);
    }
    // ---- GEMM2: S = sigmoid(zM @ e^T) ----
    {
        GemmParams p{};
        p.a[0] = p1; p.a[1] = p1; p.a[2] = p2; p.a[3] = p1; p.a[4] = p2; p.a[5] = p3;
        p.b[0] = e1; p.b[1] = e2; p.b[2] = e1; p.b[3] = e3; p.b[4] = e2; p.b[5] = e1;
        p.strideA = S8; p.strideB = S8; p.strideC = S8;
        p.C = A_out;
        mm_kernel<6, 1><<<gg, gb, SMEM_BYTES>>>(p);
    }
    // ---- Softmax over N (column axis) ----
    colsum_kernel<<<dim3(MEDIM / 256, BATCH), gb>>>(A_out, cs);
    softmax_split_kernel<<<(BATCH * S8) / 256, 256>>>(A_out, cs, a1, a2);

    // ---- GEMM3: e_out = A @ e  (limb pairs hh,hl,lh) ----
    {
        GemmParams p{};
        p.a[0] = a1; p.a[1] = a1; p.a[2] = a2;
        p.b[0] = t1; p.b[1] = t2; p.b[2] = t1;
        p.strideA = S8; p.strideB = S8; p.strideC = S8;
        p.C = e_out;
        mm_kernel<3, 0><<<gg, gb, SMEM_BYTES>>>(p);
    }
}

// round 9
// speedup vs baseline: 1.2618x; 1.2618x over previous
#include <cuda_runtime.h>
#include <cuda_bf16.h>
#include <cstdint>
#include <math.h>

// Problem constants
#define BATCH 8
#define NDIM  1024
#define MEDIM 1024
#define DDIM  1024

typedef __nv_bfloat16 bf16;

// ============================================================================
// Scratch (device globals; no allocation allowed)
// ============================================================================
#define EL8M ((size_t)BATCH * 1024 * 1024)
__device__ bf16 g_z1[EL8M], g_z2[EL8M], g_z3[EL8M];                 // z limbs [B,N,D]
__device__ bf16 g_m1[1024*1024], g_m2[1024*1024], g_m3[1024*1024];  // M^T limbs [D,D]
__device__ bf16 g_p1[EL8M], g_p2[EL8M], g_p3[EL8M];                 // zM limbs [B,N,D]
__device__ bf16 g_e1[EL8M], g_e2[EL8M], g_e3[EL8M];                 // e limbs [B,ME,D]
__device__ bf16 g_t1[EL8M], g_t2[EL8M];                             // e^T limbs [B,D,ME]
__device__ bf16 g_a1[EL8M], g_a2[EL8M];                             // A limbs [B,N,ME]
__device__ float g_colsum[BATCH * MEDIM];

// ============================================================================
// PTX helpers (compute_103-safe: mma.sync / ldmatrix / cp.async only)
// ============================================================================
__device__ __forceinline__ uint32_t smem_u32(const void* p) {
    uint32_t a;
    asm("{ .reg .u64 t; cvta.to.shared.u64 t, %1; cvt.u32.u64 %0, t; }" : "=r"(a) : "l"(p));
    return a;
}

#define CP_ASYNC16(dst, src) \
    asm volatile("cp.async.cg.shared.global [%0], [%1], 16;" :: "r"(dst), "l"(src))
#define CP_COMMIT() asm volatile("cp.async.commit_group;" ::: "memory")
#define CP_WAIT4()  asm volatile("cp.async.wait_group 4;" ::: "memory")

#define LDMATRIX_X4(r, addr) \
    asm volatile("ldmatrix.sync.aligned.m8n8.x4.shared.b16 {%0,%1,%2,%3}, [%4];" \
        : "=r"((r)[0]), "=r"((r)[1]), "=r"((r)[2]), "=r"((r)[3]) : "r"(addr))

#define MMA16816(d, a, b0, b1) \
    asm volatile("mma.sync.aligned.m16n8k16.row.col.f32.bf16.bf16.f32 " \
        "{%0,%1,%2,%3}, {%4,%5,%6,%7}, {%8,%9}, {%0,%1,%2,%3};" \
        : "+f"((d)[0]), "+f"((d)[1]), "+f"((d)[2]), "+f"((d)[3]) \
        : "r"((a)[0]), "r"((a)[1]), "r"((a)[2]), "r"((a)[3]), "r"(b0), "r"(b1))

// 64-byte-row swizzle (Swizzle<2,4,3>): bits[5:4] ^= bits[8:7]
#define SWZ64(x) ((x) ^ (((x) >> 3) & 0x30))
// 128-byte-row swizzle (used by 32x33-tile transposers only via linear stores)
#define SWZ(x) ((x) ^ (((x) >> 3) & 0x70))

// ============================================================================
// Split helpers
// ============================================================================
__device__ __forceinline__ void split3f(float v, bf16& h, bf16& m, bf16& l) {
    h = __float2bfloat16(v);
    float r = v - __bfloat162float(h);
    m = __float2bfloat16(r);
    l = __float2bfloat16(r - __bfloat162float(m));
}
__device__ __forceinline__ void split2f(float v, bf16& h, bf16& l) {
    h = __float2bfloat16(v);
    l = __float2bfloat16(v - __bfloat162float(h));
}

__global__ void split3_kernel(const float* __restrict__ x, bf16* __restrict__ h,
                              bf16* __restrict__ m, bf16* __restrict__ l) {
    size_t i = (size_t)blockIdx.x * blockDim.x + threadIdx.x;
    split3f(x[i], h[i], m[i], l[i]);
}

// transpose + 3-split (single 1024x1024 matrix): out[r][c] = in[c][r]
__global__ void tsplit3_kernel(const float* __restrict__ x, bf16* __restrict__ h,
                               bf16* __restrict__ m, bf16* __restrict__ l) {
    __shared__ float tile[32][33];
    int x0 = blockIdx.x * 32, y0 = blockIdx.y * 32;
    for (int i = threadIdx.y; i < 32; i += 8)
        tile[i][threadIdx.x] = x[(size_t)(y0 + i) * 1024 + x0 + threadIdx.x];
    __syncthreads();
    for (int i = threadIdx.y; i < 32; i += 8) {
        float v = tile[threadIdx.x][i];
        size_t o = (size_t)(x0 + i) * 1024 + y0 + threadIdx.x;
        split3f(v, h[o], m[o], l[o]);
    }
}

// batched transpose + 2-split: out[b][r][c] = in[b][c][r]
__global__ void tsplit2_kernel(const float* __restrict__ x, bf16* __restrict__ h,
                               bf16* __restrict__ l) {
    __shared__ float tile[32][33];
    size_t boff = (size_t)blockIdx.z * 1024 * 1024;
    int x0 = blockIdx.x * 32, y0 = blockIdx.y * 32;
    for (int i = threadIdx.y; i < 32; i += 8)
        tile[i][threadIdx.x] = x[boff + (size_t)(y0 + i) * 1024 + x0 + threadIdx.x];
    __syncthreads();
    for (int i = threadIdx.y; i < 32; i += 8) {
        float v = tile[threadIdx.x][i];
        size_t o = boff + (size_t)(x0 + i) * 1024 + y0 + threadIdx.x;
        split2f(v, h[o], l[o]);
    }
}

// ============================================================================
// bf16 tensor-core GEMM (mma.sync m16n8k16), Ozaki multi-segment K.
// CTA tile 128x256, warp tile 64x64 (8 warps, 2x4), BK=32, 6-stage cp.async,
// single barrier per chunk.
// C[128x256 tile] = sum_seg A_seg[128,1024] @ B_seg[256,1024]^T
// Both operands K-major bf16. EPI: 0=f32 store, 1=sigmoid f32, 2=3-limb bf16.
// ============================================================================
struct GemmParams {
    const bf16* a[6];
    const bf16* b[6];
    long strideA, strideB, strideC;
    float* C;
    bf16 *oh, *om, *ol;
};

#define STAGE_BYTES 24576u   // A 8KB + B 16KB
#define NSTAGE 6
#define SMEM_BYTES 147456    // 6 stages

template <int NSEG, int EPI>
__global__ void __launch_bounds__(256, 1) mm_kernel(GemmParams p) {
    extern __shared__ char smem[];
    const uint32_t sb = smem_u32(smem);
    const int tid = threadIdx.x;
    const int lid = tid & 31;
    const int wid = tid >> 5;
    const int wm = wid & 1;    // 0..1 -> 64-row slice
    const int wn = wid >> 1;   // 0..3 -> 64-col slice

    const int b = blockIdx.z;
    const long row0 = (long)blockIdx.y * 128;
    const long col0 = (long)blockIdx.x * 256;

    const int NCH = NSEG * 32;   // K chunks of 32

    float acc[4][8][4];
#pragma unroll
    for (int i = 0; i < 4; i++)
#pragma unroll
        for (int j = 0; j < 8; j++)
#pragma unroll
            for (int k = 0; k < 4; k++) acc[i][j][k] = 0.0f;

    // Per chunk: A 128x32 bf16 = 8KB (512 x16B), B 256x32 = 16KB (1024 x16B).
    auto load_chunk = [&](int c, int stage) {
        const int seg = c >> 5;
        const long kk = (long)(c & 31) << 5;
        const bf16* Ag = p.a[seg] + (long)b * p.strideA + kk;
        const bf16* Bg = p.b[seg] + (long)b * p.strideB + kk;
        const uint32_t sa = sb + (uint32_t)stage * STAGE_BYTES;
        const uint32_t sbb = sa + 8192u;
#pragma unroll
        for (int t = 0; t < 2; t++) {           // A: 512 transfers
            int idx = tid + (t << 8);
            int r = idx >> 2;                   // 0..127
            int c16 = idx & 3;                  // 16B unit in 64B row
            uint32_t bo = (uint32_t)(r << 6) + (uint32_t)(c16 << 4);
            CP_ASYNC16(sa + SWZ64(bo), Ag + (row0 + r) * 1024 + (c16 << 3));
        }
#pragma unroll
        for (int t = 0; t < 4; t++) {           // B: 1024 transfers
            int idx = tid + (t << 8);
            int r = idx >> 2;                   // 0..255
            int c16 = idx & 3;
            uint32_t bo = (uint32_t)(r << 6) + (uint32_t)(c16 << 4);
            CP_ASYNC16(sbb + SWZ64(bo), Bg + (col0 + r) * 1024 + (c16 << 3));
        }
    };

    // Prologue: fill 5 stages (NCH >= 96 always)
#pragma unroll
    for (int i = 0; i < NSTAGE - 1; i++) { load_chunk(i, i); CP_COMMIT(); }

    for (int c = 0; c < NCH; c++) {
        CP_WAIT4();          // chunk c resident (5 groups always outstanding)
        __syncthreads();     // all warps see chunk c; all warps done with c-1
        if (c + NSTAGE - 1 < NCH) load_chunk(c + NSTAGE - 1, (c + NSTAGE - 1) % NSTAGE);
        CP_COMMIT();         // unconditional: keeps group accounting in the tail

        const uint32_t sa  = sb + (uint32_t)(c % NSTAGE) * STAGE_BYTES;
        const uint32_t sbb = sa + 8192u;

#pragma unroll
        for (int j = 0; j < 2; j++) {       // k16 step within 32-chunk
            uint32_t af[4][4];
#pragma unroll
            for (int mi = 0; mi < 4; mi++) {
                int row = wm * 64 + mi * 16 + (lid & 15);
                uint32_t bo = (uint32_t)(row << 6) + (uint32_t)(j << 5)
                            + (uint32_t)((lid >> 4) << 4);
                LDMATRIX_X4(af[mi], sa + SWZ64(bo));
            }
#pragma unroll
            for (int ni = 0; ni < 4; ni++) {  // 16-col groups
                uint32_t bfr[4];
                int nr = wn * 64 + ni * 16 + (lid & 7) + (((lid >> 4) & 1) << 3);
                uint32_t bo = (uint32_t)(nr << 6) + (uint32_t)(j << 5)
                            + (uint32_t)(((lid >> 3) & 1) << 4);
                LDMATRIX_X4(bfr, sbb + SWZ64(bo));
#pragma unroll
                for (int mi = 0; mi < 4; mi++) {
                    MMA16816(acc[mi][ni * 2 + 0], af[mi], bfr[0], bfr[1]);
                    MMA16816(acc[mi][ni * 2 + 1], af[mi], bfr[2], bfr[3]);
                }
            }
        }
    }

    // ---- Epilogue (direct from registers) ----
    const int r_in = lid >> 2;
    const int c_in = (lid & 3) << 1;
#pragma unroll
    for (int mi = 0; mi < 4; mi++) {
        const long row = row0 + wm * 64 + mi * 16 + r_in;
#pragma unroll
        for (int nj = 0; nj < 8; nj++) {
            const long colg = col0 + wn * 64 + nj * 8 + c_in;
            float v0 = acc[mi][nj][0], v1 = acc[mi][nj][1];
            float v2 = acc[mi][nj][2], v3 = acc[mi][nj][3];
            if (EPI == 0 || EPI == 1) {
                if (EPI == 1) {
                    v0 = 1.0f / (1.0f + expf(-v0));
                    v1 = 1.0f / (1.0f + expf(-v1));
                    v2 = 1.0f / (1.0f + expf(-v2));
                    v3 = 1.0f / (1.0f + expf(-v3));
                }
                float* Cp = p.C + (long)b * p.strideC;
                *reinterpret_cast<float2*>(Cp + row * 1024 + colg)       = make_float2(v0, v1);
                *reinterpret_cast<float2*>(Cp + (row + 8) * 1024 + colg) = make_float2(v2, v3);
            } else {
                const long base0 = (long)b * p.strideC + row * 1024 + colg;
                const long base1 = base0 + 8 * 1024;
                bf16 h0, m0, l0, h1, m1, l1;
                split3f(v0, h0, m0, l0); split3f(v1, h1, m1, l1);
                *reinterpret_cast<__nv_bfloat162*>(p.oh + base0) = __nv_bfloat162(h0, h1);
                *reinterpret_cast<__nv_bfloat162*>(p.om + base0) = __nv_bfloat162(m0, m1);
                *reinterpret_cast<__nv_bfloat162*>(p.ol + base0) = __nv_bfloat162(l0, l1);
                split3f(v2, h0, m0, l0); split3f(v3, h1, m1, l1);
                *reinterpret_cast<__nv_bfloat162*>(p.oh + base1) = __nv_bfloat162(h0, h1);
                *reinterpret_cast<__nv_bfloat162*>(p.om + base1) = __nv_bfloat162(m0, m1);
                *reinterpret_cast<__nv_bfloat162*>(p.ol + base1) = __nv_bfloat162(l0, l1);
            }
        }
    }
}

// ============================================================================
// Softmax pieces
// ============================================================================
__global__ void colsum_kernel(const float* __restrict__ S, float* __restrict__ cs) {
    int b = blockIdx.y;
    int m = blockIdx.x * blockDim.x + threadIdx.x;
    const float* p = S + (size_t)b * NDIM * MEDIM + m;
    float s = 0.0f;
#pragma unroll 4
    for (int n = 0; n < NDIM; n++) s += expf(p[(size_t)n * MEDIM]);
    cs[b * MEDIM + m] = s;
}

// A = exp(S)/colsum (in place), plus 2-limb bf16 split of A
__global__ void softmax_split_kernel(float* __restrict__ S, const float* __restrict__ cs,
                                     bf16* __restrict__ ah, bf16* __restrict__ al) {
    size_t g = (size_t)blockIdx.x * blockDim.x + threadIdx.x;
    int b = (int)(g >> 20);
    int m = (int)(g & (MEDIM - 1));
    float v = expf(S[g]) / cs[b * MEDIM + m];
    S[g] = v;
    split2f(v, ah[g], al[g]);
}

// ============================================================================
// Host launch
// ============================================================================
extern "C" void kernel_launch(void* const* d_in, const int* in_sizes, int n_in,
                              void* d_out, int out_size) {
    const float* z = (const float*)d_in[0];
    const float* e = (const float*)d_in[1];
    const float* M = (const float*)d_in[2];

    float* e_out = (float*)d_out;
    float* A_out = (float*)d_out + (size_t)BATCH * NDIM * DDIM;

    bf16 *z1, *z2, *z3, *m1, *m2, *m3, *p1, *p2, *p3, *e1, *e2, *e3, *t1, *t2, *a1, *a2;
    float* cs;
    cudaGetSymbolAddress((void**)&z1, g_z1); cudaGetSymbolAddress((void**)&z2, g_z2);
    cudaGetSymbolAddress((void**)&z3, g_z3);
    cudaGetSymbolAddress((void**)&m1, g_m1); cudaGetSymbolAddress((void**)&m2, g_m2);
    cudaGetSymbolAddress((void**)&m3, g_m3);
    cudaGetSymbolAddress((void**)&p1, g_p1); cudaGetSymbolAddress((void**)&p2, g_p2);
    cudaGetSymbolAddress((void**)&p3, g_p3);
    cudaGetSymbolAddress((void**)&e1, g_e1); cudaGetSymbolAddress((void**)&e2, g_e2);
    cudaGetSymbolAddress((void**)&e3, g_e3);
    cudaGetSymbolAddress((void**)&t1, g_t1); cudaGetSymbolAddress((void**)&t2, g_t2);
    cudaGetSymbolAddress((void**)&a1, g_a1); cudaGetSymbolAddress((void**)&a2, g_a2);
    cudaGetSymbolAddress((void**)&cs, g_colsum);

    cudaFuncSetAttribute(mm_kernel<6, 2>, cudaFuncAttributeMaxDynamicSharedMemorySize, SMEM_BYTES);
    cudaFuncSetAttribute(mm_kernel<6, 1>, cudaFuncAttributeMaxDynamicSharedMemorySize, SMEM_BYTES);
    cudaFuncSetAttribute(mm_kernel<3, 0>, cudaFuncAttributeMaxDynamicSharedMemorySize, SMEM_BYTES);

    const long S8 = (long)1024 * 1024;

    // ---- Prep: limb splits ----
    split3_kernel<<<(BATCH * S8) / 256, 256>>>(z, z1, z2, z3);
    split3_kernel<<<(BATCH * S8) / 256, 256>>>(e, e1, e2, e3);
    tsplit3_kernel<<<dim3(32, 32, 1), dim3(32, 8)>>>(M, m1, m2, m3);
    tsplit2_kernel<<<dim3(32, 32, BATCH), dim3(32, 8)>>>(e, t1, t2);

    dim3 gg(4, 8, BATCH);   // cols/256, rows/128, batch
    dim3 gb(256);

    // ---- GEMM1: zM = z @ M  (limb pairs hh,hm,mh,hl,mm,lh) -> zM limbs ----
    {
        GemmParams p{};
        p.a[0] = z1; p.a[1] = z1; p.a[2] = z2; p.a[3] = z1; p.a[4] = z2; p.a[5] = z3;
        p.b[0] = m1; p.b[1] = m2; p.b[2] = m1; p.b[3] = m3; p.b[4] = m2; p.b[5] = m1;
        p.strideA = S8; p.strideB = 0; p.strideC = S8;
        p.oh = p1; p.om = p2; p.ol = p3; p.C = nullptr;
        mm_kernel<6, 2><<<gg, gb, SMEM_BYTES>>>(p);
    }
    // ---- GEMM2: S = sigmoid(zM @ e^T) ----
    {
        GemmParams p{};
        p.a[0] = p1; p.a[1] = p1; p.a[2] = p2; p.a[3] = p1; p.a[4] = p2; p.a[5] = p3;
        p.b[0] = e1; p.b[1] = e2; p.b[2] = e1; p.b[3] = e3; p.b[4] = e2; p.b[5] = e1;
        p.strideA = S8; p.strideB = S8; p.strideC = S8;
        p.C = A_out;
        mm_kernel<6, 1><<<gg, gb, SMEM_BYTES>>>(p);
    }
    // ---- Softmax over N (column axis) ----
    colsum_kernel<<<dim3(MEDIM / 256, BATCH), gb>>>(A_out, cs);
    softmax_split_kernel<<<(BATCH * S8) / 256, 256>>>(A_out, cs, a1, a2);

    // ---- GEMM3: e_out = A @ e  (limb pairs hh,hl,lh) ----
    {
        GemmParams p{};
        p.a[0] = a1; p.a[1] = a1; p.a[2] = a2;
        p.b[0] = t1; p.b[1] = t2; p.b[2] = t1;
        p.strideA = S8; p.strideB = S8; p.strideC = S8;
        p.C = e_out;
        mm_kernel<3, 0><<<gg, gb, SMEM_BYTES>>>(p);
    }
}

// round 10
// speedup vs baseline: 2.1618x; 1.7132x over previous
#include <cuda_runtime.h>
#include <cuda_fp16.h>
#include <cstdint>
#include <math.h>

// Problem constants
#define BATCH 8
#define NDIM  1024
#define MEDIM 1024
#define DDIM  1024

typedef __half hf;

// ============================================================================
// Scratch (device globals; no allocation allowed)
// ============================================================================
#define EL8M ((size_t)BATCH * 1024 * 1024)
__device__ hf g_z1[EL8M], g_z2[EL8M];               // z limbs [B,N,D]
__device__ hf g_m1[1024*1024], g_m2[1024*1024];     // M^T limbs [D,D]
__device__ hf g_p1[EL8M], g_p2[EL8M];               // zM limbs [B,N,D]
__device__ hf g_e1[EL8M], g_e2[EL8M];               // e limbs [B,ME,D]
__device__ hf g_t1[EL8M], g_t2[EL8M];               // e^T limbs [B,D,ME]
__device__ hf g_a1[EL8M], g_a2[EL8M];               // A limbs [B,N,ME]
__device__ float g_colsum[BATCH * MEDIM];

// ============================================================================
// PTX helpers (compute_103-safe: mma.sync / ldmatrix / cp.async only)
// ============================================================================
__device__ __forceinline__ uint32_t smem_u32(const void* p) {
    uint32_t a;
    asm("{ .reg .u64 t; cvta.to.shared.u64 t, %1; cvt.u32.u64 %0, t; }" : "=r"(a) : "l"(p));
    return a;
}

#define CP_ASYNC16(dst, src) \
    asm volatile("cp.async.cg.shared.global [%0], [%1], 16;" :: "r"(dst), "l"(src))
#define CP_COMMIT() asm volatile("cp.async.commit_group;" ::: "memory")
#define CP_WAIT1()  asm volatile("cp.async.wait_group 1;" ::: "memory")

#define LDMATRIX_X4(r, addr) \
    asm volatile("ldmatrix.sync.aligned.m8n8.x4.shared.b16 {%0,%1,%2,%3}, [%4];" \
        : "=r"((r)[0]), "=r"((r)[1]), "=r"((r)[2]), "=r"((r)[3]) : "r"(addr))

#define MMA16816(d, a, b0, b1) \
    asm volatile("mma.sync.aligned.m16n8k16.row.col.f32.f16.f16.f32 " \
        "{%0,%1,%2,%3}, {%4,%5,%6,%7}, {%8,%9}, {%0,%1,%2,%3};" \
        : "+f"((d)[0]), "+f"((d)[1]), "+f"((d)[2]), "+f"((d)[3]) \
        : "r"((a)[0]), "r"((a)[1]), "r"((a)[2]), "r"((a)[3]), "r"(b0), "r"(b1))

#define SWZ(x) ((x) ^ (((x) >> 3) & 0x70))

// ============================================================================
// Split helpers: fp32 -> 2 fp16 limbs (22 mantissa bits captured)
// ============================================================================
__device__ __forceinline__ void split2h(float v, hf& h, hf& l) {
    h = __float2half_rn(v);
    l = __float2half_rn(v - __half2float(h));
}

__global__ void split2_kernel(const float* __restrict__ x, hf* __restrict__ h,
                              hf* __restrict__ l) {
    size_t i = (size_t)blockIdx.x * blockDim.x + threadIdx.x;
    split2h(x[i], h[i], l[i]);
}

// batched transpose + 2-split: out[b][r][c] = in[b][c][r] (use gridDim.z=1 for M)
__global__ void tsplit2_kernel(const float* __restrict__ x, hf* __restrict__ h,
                               hf* __restrict__ l) {
    __shared__ float tile[32][33];
    size_t boff = (size_t)blockIdx.z * 1024 * 1024;
    int x0 = blockIdx.x * 32, y0 = blockIdx.y * 32;
    for (int i = threadIdx.y; i < 32; i += 8)
        tile[i][threadIdx.x] = x[boff + (size_t)(y0 + i) * 1024 + x0 + threadIdx.x];
    __syncthreads();
    for (int i = threadIdx.y; i < 32; i += 8) {
        float v = tile[threadIdx.x][i];
        size_t o = boff + (size_t)(x0 + i) * 1024 + y0 + threadIdx.x;
        split2h(v, h[o], l[o]);
    }
}

// ============================================================================
// fp16 tensor-core GEMM (mma.sync m16n8k16), 3 limb-pair segments.
// CTA tile 128x128, warp tile 32x64 (8 warps, 4x2), BK=64, 3-stage cp.async,
// single barrier per chunk. C = sum_seg A_seg[128,1024] @ B_seg[128,1024]^T
// EPI: 0 = f32 store, 1 = sigmoid f32, 2 = 2-limb fp16 split.
// ============================================================================
struct GemmParams {
    const hf* a[3];
    const hf* b[3];
    long strideA, strideB, strideC;
    float* C;
    hf *oh, *ol;
};

#define STAGE_BYTES 32768u   // A 16KB + B 16KB
#define SMEM_BYTES  98304    // 3 stages

template <int EPI>
__global__ void __launch_bounds__(256, 2) mm_kernel(GemmParams p) {
    extern __shared__ char smem[];
    const uint32_t sb = smem_u32(smem);
    const int tid = threadIdx.x;
    const int lid = tid & 31;
    const int wid = tid >> 5;
    const int wm = wid & 3;    // 0..3 -> 32-row slice
    const int wn = wid >> 2;   // 0..1 -> 64-col slice

    const int b = blockIdx.z;
    const long row0 = (long)blockIdx.y * 128;
    const long col0 = (long)blockIdx.x * 128;

    const int NCH = 48;   // 3 segments x 16 chunks of 64

    float acc[2][8][4];
#pragma unroll
    for (int i = 0; i < 2; i++)
#pragma unroll
        for (int j = 0; j < 8; j++)
#pragma unroll
            for (int k = 0; k < 4; k++) acc[i][j][k] = 0.0f;

    // Per chunk: A 128x64 fp16 = 16KB (1024 x16B), B same. 4 iters/thread each.
    auto load_chunk = [&](int c, int stage) {
        const int seg = c >> 4;
        const long kk = (long)(c & 15) << 6;
        const hf* Ag = p.a[seg] + (long)b * p.strideA + kk;
        const hf* Bg = p.b[seg] + (long)b * p.strideB + kk;
        const uint32_t sa = sb + (uint32_t)stage * STAGE_BYTES;
        const uint32_t sbb = sa + 16384u;
#pragma unroll
        for (int t = 0; t < 4; t++) {
            int idx = tid + (t << 8);          // 0..1023
            int r = idx >> 3;                  // 0..127
            int c16 = idx & 7;                 // 16B unit in 128B row
            uint32_t bo = (uint32_t)(r << 7) + (uint32_t)(c16 << 4);
            CP_ASYNC16(sa  + SWZ(bo), Ag + (row0 + r) * 1024 + (c16 << 3));
            CP_ASYNC16(sbb + SWZ(bo), Bg + (col0 + r) * 1024 + (c16 << 3));
        }
    };

    load_chunk(0, 0); CP_COMMIT();
    load_chunk(1, 1); CP_COMMIT();

    for (int c = 0; c < NCH; c++) {
        CP_WAIT1();          // chunk c resident (only chunk c+1 may be pending)
        __syncthreads();     // all warps: done with chunk c-1, see chunk c
        if (c + 2 < NCH) load_chunk(c + 2, (c + 2) % 3);
        CP_COMMIT();         // unconditional: keeps group accounting in tail

        const uint32_t sa  = sb + (uint32_t)(c % 3) * STAGE_BYTES;
        const uint32_t sbb = sa + 16384u;

#pragma unroll
        for (int j = 0; j < 4; j++) {       // k16 step within 64-chunk
            uint32_t af[2][4];
#pragma unroll
            for (int mi = 0; mi < 2; mi++) {
                int row = wm * 32 + mi * 16 + (lid & 15);
                uint32_t bo = (uint32_t)(row << 7) + (uint32_t)(j << 5)
                            + (uint32_t)((lid >> 4) << 4);
                LDMATRIX_X4(af[mi], sa + SWZ(bo));
            }
#pragma unroll
            for (int ni = 0; ni < 4; ni++) {  // 16-col groups
                uint32_t bfr[4];
                int nr = wn * 64 + ni * 16 + (lid & 7) + (((lid >> 4) & 1) << 3);
                uint32_t bo = (uint32_t)(nr << 7) + (uint32_t)(j << 5)
                            + (uint32_t)(((lid >> 3) & 1) << 4);
                LDMATRIX_X4(bfr, sbb + SWZ(bo));
#pragma unroll
                for (int mi = 0; mi < 2; mi++) {
                    MMA16816(acc[mi][ni * 2 + 0], af[mi], bfr[0], bfr[1]);
                    MMA16816(acc[mi][ni * 2 + 1], af[mi], bfr[2], bfr[3]);
                }
            }
        }
    }

    // ---- Epilogue (direct from registers) ----
    const int r_in = lid >> 2;
    const int c_in = (lid & 3) << 1;
#pragma unroll
    for (int mi = 0; mi < 2; mi++) {
        const long row = row0 + wm * 32 + mi * 16 + r_in;
#pragma unroll
        for (int nj = 0; nj < 8; nj++) {
            const long colg = col0 + wn * 64 + nj * 8 + c_in;
            float v0 = acc[mi][nj][0], v1 = acc[mi][nj][1];
            float v2 = acc[mi][nj][2], v3 = acc[mi][nj][3];
            if (EPI == 0 || EPI == 1) {
                if (EPI == 1) {
                    v0 = 1.0f / (1.0f + expf(-v0));
                    v1 = 1.0f / (1.0f + expf(-v1));
                    v2 = 1.0f / (1.0f + expf(-v2));
                    v3 = 1.0f / (1.0f + expf(-v3));
                }
                float* Cp = p.C + (long)b * p.strideC;
                *reinterpret_cast<float2*>(Cp + row * 1024 + colg)       = make_float2(v0, v1);
                *reinterpret_cast<float2*>(Cp + (row + 8) * 1024 + colg) = make_float2(v2, v3);
            } else {
                const long base0 = (long)b * p.strideC + row * 1024 + colg;
                const long base1 = base0 + 8 * 1024;
                hf h0, l0, h1, l1;
                split2h(v0, h0, l0); split2h(v1, h1, l1);
                *reinterpret_cast<__half2*>(p.oh + base0) = __halves2half2(h0, h1);
                *reinterpret_cast<__half2*>(p.ol + base0) = __halves2half2(l0, l1);
                split2h(v2, h0, l0); split2h(v3, h1, l1);
                *reinterpret_cast<__half2*>(p.oh + base1) = __halves2half2(h0, h1);
                *reinterpret_cast<__half2*>(p.ol + base1) = __halves2half2(l0, l1);
            }
        }
    }
}

// ============================================================================
// Softmax pieces
// ============================================================================
__global__ void colsum_kernel(const float* __restrict__ S, float* __restrict__ cs) {
    int b = blockIdx.y;
    int m = blockIdx.x * blockDim.x + threadIdx.x;
    const float* p = S + (size_t)b * NDIM * MEDIM + m;
    float s = 0.0f;
#pragma unroll 4
    for (int n = 0; n < NDIM; n++) s += expf(p[(size_t)n * MEDIM]);
    cs[b * MEDIM + m] = s;
}

// A = exp(S)/colsum (in place), plus 2-limb fp16 split of A
__global__ void softmax_split_kernel(float* __restrict__ S, const float* __restrict__ cs,
                                     hf* __restrict__ ah, hf* __restrict__ al) {
    size_t g = (size_t)blockIdx.x * blockDim.x + threadIdx.x;
    int b = (int)(g >> 20);
    int m = (int)(g & (MEDIM - 1));
    float v = expf(S[g]) / cs[b * MEDIM + m];
    S[g] = v;
    split2h(v, ah[g], al[g]);
}

// ============================================================================
// Host launch
// ============================================================================
extern "C" void kernel_launch(void* const* d_in, const int* in_sizes, int n_in,
                              void* d_out, int out_size) {
    const float* z = (const float*)d_in[0];
    const float* e = (const float*)d_in[1];
    const float* M = (const float*)d_in[2];

    float* e_out = (float*)d_out;
    float* A_out = (float*)d_out + (size_t)BATCH * NDIM * DDIM;

    hf *z1, *z2, *m1, *m2, *p1, *p2, *e1, *e2, *t1, *t2, *a1, *a2;
    float* cs;
    cudaGetSymbolAddress((void**)&z1, g_z1); cudaGetSymbolAddress((void**)&z2, g_z2);
    cudaGetSymbolAddress((void**)&m1, g_m1); cudaGetSymbolAddress((void**)&m2, g_m2);
    cudaGetSymbolAddress((void**)&p1, g_p1); cudaGetSymbolAddress((void**)&p2, g_p2);
    cudaGetSymbolAddress((void**)&e1, g_e1); cudaGetSymbolAddress((void**)&e2, g_e2);
    cudaGetSymbolAddress((void**)&t1, g_t1); cudaGetSymbolAddress((void**)&t2, g_t2);
    cudaGetSymbolAddress((void**)&a1, g_a1); cudaGetSymbolAddress((void**)&a2, g_a2);
    cudaGetSymbolAddress((void**)&cs, g_colsum);

    cudaFuncSetAttribute(mm_kernel<2>, cudaFuncAttributeMaxDynamicSharedMemorySize, SMEM_BYTES);
    cudaFuncSetAttribute(mm_kernel<1>, cudaFuncAttributeMaxDynamicSharedMemorySize, SMEM_BYTES);
    cudaFuncSetAttribute(mm_kernel<0>, cudaFuncAttributeMaxDynamicSharedMemorySize, SMEM_BYTES);

    const long S8 = (long)1024 * 1024;

    // ---- Prep: limb splits ----
    split2_kernel<<<(BATCH * S8) / 256, 256>>>(z, z1, z2);
    split2_kernel<<<(BATCH * S8) / 256, 256>>>(e, e1, e2);
    tsplit2_kernel<<<dim3(32, 32, 1), dim3(32, 8)>>>(M, m1, m2);
    tsplit2_kernel<<<dim3(32, 32, BATCH), dim3(32, 8)>>>(e, t1, t2);

    dim3 gg(8, 8, BATCH);   // cols/128, rows/128, batch
    dim3 gb(256);

    // ---- GEMM1: zM = z @ M  (pairs hh, hl, lh) -> zM fp16 limbs ----
    {
        GemmParams p{};
        p.a[0] = z1; p.a[1] = z1; p.a[2] = z2;
        p.b[0] = m1; p.b[1] = m2; p.b[2] = m1;
        p.strideA = S8; p.strideB = 0; p.strideC = S8;
        p.oh = p1; p.ol = p2; p.C = nullptr;
        mm_kernel<2><<<gg, gb, SMEM_BYTES>>>(p);
    }
    // ---- GEMM2: S = sigmoid(zM @ e^T)  (pairs hh, hl, lh) ----
    {
        GemmParams p{};
        p.a[0] = p1; p.a[1] = p1; p.a[2] = p2;
        p.b[0] = e1; p.b[1] = e2; p.b[2] = e1;
        p.strideA = S8; p.strideB = S8; p.strideC = S8;
        p.C = A_out;
        mm_kernel<1><<<gg, gb, SMEM_BYTES>>>(p);
    }
    // ---- Softmax over N (column axis) ----
    colsum_kernel<<<dim3(MEDIM / 256, BATCH), gb>>>(A_out, cs);
    softmax_split_kernel<<<(BATCH * S8) / 256, 256>>>(A_out, cs, a1, a2);

    // ---- GEMM3: e_out = A @ e  (pairs hh, hl, lh) ----
    {
        GemmParams p{};
        p.a[0] = a1; p.a[1] = a1; p.a[2] = a2;
        p.b[0] = t1; p.b[1] = t2; p.b[2] = t1;
        p.strideA = S8; p.strideB = S8; p.strideC = S8;
        p.C = e_out;
        mm_kernel<0><<<gg, gb, SMEM_BYTES>>>(p);
    }
}

// round 12
// speedup vs baseline: 2.1619x; 1.0000x over previous
#include <cuda_runtime.h>
#include <cuda_fp16.h>
#include <cstdint>
#include <math.h>

// Problem constants
#define BATCH 8
#define NDIM  1024
#define MEDIM 1024
#define DDIM  1024

typedef __half hf;

// ============================================================================
// Scratch (device globals; no allocation allowed)
// ============================================================================
#define EL8M ((size_t)BATCH * 1024 * 1024)
__device__ hf g_z1[EL8M], g_z2[EL8M];               // z limbs [B,N,D]
__device__ hf g_m1[1024*1024], g_m2[1024*1024];     // M^T limbs [D,D]
__device__ hf g_p1[EL8M], g_p2[EL8M];               // zM limbs [B,N,D]
__device__ hf g_e1[EL8M], g_e2[EL8M];               // e limbs [B,ME,D]
__device__ hf g_t1[EL8M], g_t2[EL8M];               // e^T limbs [B,D,ME]
__device__ hf g_a1[EL8M], g_a2[EL8M];               // A limbs [B,N,ME]
__device__ float g_colsum[BATCH * MEDIM];

// ============================================================================
// PTX helpers (compute_103-safe: mma.sync / ldmatrix / cp.async only)
// ============================================================================
__device__ __forceinline__ uint32_t smem_u32(const void* p) {
    uint32_t a;
    asm("{ .reg .u64 t; cvta.to.shared.u64 t, %1; cvt.u32.u64 %0, t; }" : "=r"(a) : "l"(p));
    return a;
}

#define CP_ASYNC16(dst, src) \
    asm volatile("cp.async.cg.shared.global [%0], [%1], 16;" :: "r"(dst), "l"(src))
#define CP_COMMIT() asm volatile("cp.async.commit_group;" ::: "memory")
#define CP_WAIT1()  asm volatile("cp.async.wait_group 1;" ::: "memory")

#define LDMATRIX_X4(r, addr) \
    asm volatile("ldmatrix.sync.aligned.m8n8.x4.shared.b16 {%0,%1,%2,%3}, [%4];" \
        : "=r"((r)[0]), "=r"((r)[1]), "=r"((r)[2]), "=r"((r)[3]) : "r"(addr))

#define MMA16816(d, a, b0, b1) \
    asm volatile("mma.sync.aligned.m16n8k16.row.col.f32.f16.f16.f32 " \
        "{%0,%1,%2,%3}, {%4,%5,%6,%7}, {%8,%9}, {%0,%1,%2,%3};" \
        : "+f"((d)[0]), "+f"((d)[1]), "+f"((d)[2]), "+f"((d)[3]) \
        : "r"((a)[0]), "r"((a)[1]), "r"((a)[2]), "r"((a)[3]), "r"(b0), "r"(b1))

// 64-byte-row swizzle (Swizzle<2,4,3>): bits[5:4] ^= bits[8:7]
#define SWZ64(x) ((x) ^ (((x) >> 3) & 0x30))

// ============================================================================
// Split helpers: fp32 -> 2 fp16 limbs (22 mantissa bits captured)
// ============================================================================
__device__ __forceinline__ void split2h(float v, hf& h, hf& l) {
    h = __float2half_rn(v);
    l = __float2half_rn(v - __half2float(h));
}

__global__ void split2_kernel(const float* __restrict__ x, hf* __restrict__ h,
                              hf* __restrict__ l) {
    size_t i = (size_t)blockIdx.x * blockDim.x + threadIdx.x;
    split2h(x[i], h[i], l[i]);
}

// batched transpose + 2-split: out[b][r][c] = in[b][c][r] (gridDim.z=1 for M)
__global__ void tsplit2_kernel(const float* __restrict__ x, hf* __restrict__ h,
                               hf* __restrict__ l) {
    __shared__ float tile[32][33];
    size_t boff = (size_t)blockIdx.z * 1024 * 1024;
    int x0 = blockIdx.x * 32, y0 = blockIdx.y * 32;
    for (int i = threadIdx.y; i < 32; i += 8)
        tile[i][threadIdx.x] = x[boff + (size_t)(y0 + i) * 1024 + x0 + threadIdx.x];
    __syncthreads();
    for (int i = threadIdx.y; i < 32; i += 8) {
        float v = tile[threadIdx.x][i];
        size_t o = boff + (size_t)(x0 + i) * 1024 + y0 + threadIdx.x;
        split2h(v, h[o], l[o]);
    }
}

// ============================================================================
// Fused-limb fp16 GEMM: C = a1@b1^T + a1@b2^T + a2@b1^T (fp32 accum)
// CTA tile 128x128, warp tile 32x64 (8 warps, 4x2), BK=32, 3-stage cp.async,
// single barrier per chunk. All 4 limb tiles loaded once per chunk;
// 3 MMA combos issued from the same SMEM residency.
// EPI: 0 = f32 store, 1 = sigmoid f32, 2 = 2-limb fp16 split.
// ============================================================================
struct GemmParams {
    const hf *a1, *a2, *b1, *b2;
    long strideA, strideB, strideC;
    float* C;
    hf *oh, *ol;
};

// Stage: A1 8KB | A2 8KB | B1 8KB | B2 8KB = 32KB
#define STAGE_BYTES 32768u
#define SMEM_BYTES  98304    // 3 stages

template <int EPI>
__global__ void __launch_bounds__(256, 2) mm_kernel(GemmParams p) {
    extern __shared__ char smem[];
    const uint32_t sb = smem_u32(smem);
    const int tid = threadIdx.x;
    const int lid = tid & 31;
    const int wid = tid >> 5;
    const int wm = wid & 3;    // 0..3 -> 32-row slice
    const int wn = wid >> 2;   // 0..1 -> 64-col slice

    const int b = blockIdx.z;
    const long row0 = (long)blockIdx.y * 128;
    const long col0 = (long)blockIdx.x * 128;

    const int NCH = 32;   // K chunks of 32

    float acc[2][8][4];
#pragma unroll
    for (int i = 0; i < 2; i++)
#pragma unroll
        for (int j = 0; j < 8; j++)
#pragma unroll
            for (int k = 0; k < 4; k++) acc[i][j][k] = 0.0f;

    // Per chunk: 4 tiles of 128x32 fp16 = 8KB each (512 x16B transfers).
    // 256 threads x 2 iters x 4 tiles = 2048 transfers.
    auto load_chunk = [&](int c, int stage) {
        const long kk = (long)c << 5;
        const hf* A1g = p.a1 + (long)b * p.strideA + kk;
        const hf* A2g = p.a2 + (long)b * p.strideA + kk;
        const hf* B1g = p.b1 + (long)b * p.strideB + kk;
        const hf* B2g = p.b2 + (long)b * p.strideB + kk;
        const uint32_t s0 = sb + (uint32_t)stage * STAGE_BYTES;
#pragma unroll
        for (int t = 0; t < 2; t++) {
            int idx = tid + (t << 8);          // 0..511
            int r = idx >> 2;                  // 0..127
            int c16 = idx & 3;                 // 16B unit in 64B row
            uint32_t bo = SWZ64((uint32_t)(r << 6) + (uint32_t)(c16 << 4));
            long goA = (row0 + r) * 1024 + (c16 << 3);
            long goB = (col0 + r) * 1024 + (c16 << 3);
            CP_ASYNC16(s0 + bo,          A1g + goA);
            CP_ASYNC16(s0 + 8192u + bo,  A2g + goA);
            CP_ASYNC16(s0 + 16384u + bo, B1g + goB);
            CP_ASYNC16(s0 + 24576u + bo, B2g + goB);
        }
    };

    load_chunk(0, 0); CP_COMMIT();
    load_chunk(1, 1); CP_COMMIT();

    for (int c = 0; c < NCH; c++) {
        CP_WAIT1();          // chunk c resident (only c+1 may be pending)
        __syncthreads();     // all warps: done with chunk c-1, see chunk c
        if (c + 2 < NCH) load_chunk(c + 2, (c + 2) % 3);
        CP_COMMIT();         // unconditional: keeps group accounting in tail

        const uint32_t s0 = sb + (uint32_t)(c % 3) * STAGE_BYTES;

#pragma unroll
        for (int j = 0; j < 2; j++) {       // k16 step within 32-chunk
            // A fragments: 2 limbs x 2 row-groups
            uint32_t af[2][2][4];
#pragma unroll
            for (int mi = 0; mi < 2; mi++) {
                int row = wm * 32 + mi * 16 + (lid & 15);
                uint32_t bo = SWZ64((uint32_t)(row << 6) + (uint32_t)(j << 5)
                            + (uint32_t)((lid >> 4) << 4));
                LDMATRIX_X4(af[0][mi], s0 + bo);           // a1
                LDMATRIX_X4(af[1][mi], s0 + 8192u + bo);   // a2
            }
#pragma unroll
            for (int ni = 0; ni < 4; ni++) {  // 16-col groups
                int nr = wn * 64 + ni * 16 + (lid & 7) + (((lid >> 4) & 1) << 3);
                uint32_t bo = SWZ64((uint32_t)(nr << 6) + (uint32_t)(j << 5)
                            + (uint32_t)(((lid >> 3) & 1) << 4));
                uint32_t b1f[4], b2f[4];
                LDMATRIX_X4(b1f, s0 + 16384u + bo);
                LDMATRIX_X4(b2f, s0 + 24576u + bo);
#pragma unroll
                for (int mi = 0; mi < 2; mi++) {
                    // a1*b1 (hh)
                    MMA16816(acc[mi][ni * 2 + 0], af[0][mi], b1f[0], b1f[1]);
                    MMA16816(acc[mi][ni * 2 + 1], af[0][mi], b1f[2], b1f[3]);
                    // a1*b2 (hl)
                    MMA16816(acc[mi][ni * 2 + 0], af[0][mi], b2f[0], b2f[1]);
                    MMA16816(acc[mi][ni * 2 + 1], af[0][mi], b2f[2], b2f[3]);
                    // a2*b1 (lh)
                    MMA16816(acc[mi][ni * 2 + 0], af[1][mi], b1f[0], b1f[1]);
                    MMA16816(acc[mi][ni * 2 + 1], af[1][mi], b1f[2], b1f[3]);
                }
            }
        }
    }

    // ---- Epilogue (direct from registers) ----
    const int r_in = lid >> 2;
    const int c_in = (lid & 3) << 1;
#pragma unroll
    for (int mi = 0; mi < 2; mi++) {
        const long row = row0 + wm * 32 + mi * 16 + r_in;
#pragma unroll
        for (int nj = 0; nj < 8; nj++) {
            const long colg = col0 + wn * 64 + nj * 8 + c_in;
            float v0 = acc[mi][nj][0], v1 = acc[mi][nj][1];
            float v2 = acc[mi][nj][2], v3 = acc[mi][nj][3];
            if (EPI == 0 || EPI == 1) {
                if (EPI == 1) {
                    v0 = 1.0f / (1.0f + expf(-v0));
                    v1 = 1.0f / (1.0f + expf(-v1));
                    v2 = 1.0f / (1.0f + expf(-v2));
                    v3 = 1.0f / (1.0f + expf(-v3));
                }
                float* Cp = p.C + (long)b * p.strideC;
                *reinterpret_cast<float2*>(Cp + row * 1024 + colg)       = make_float2(v0, v1);
                *reinterpret_cast<float2*>(Cp + (row + 8) * 1024 + colg) = make_float2(v2, v3);
            } else {
                const long base0 = (long)b * p.strideC + row * 1024 + colg;
                const long base1 = base0 + 8 * 1024;
                hf h0, l0, h1, l1;
                split2h(v0, h0, l0); split2h(v1, h1, l1);
                *reinterpret_cast<__half2*>(p.oh + base0) = __halves2half2(h0, h1);
                *reinterpret_cast<__half2*>(p.ol + base0) = __halves2half2(l0, l1);
                split2h(v2, h0, l0); split2h(v3, h1, l1);
                *reinterpret_cast<__half2*>(p.oh + base1) = __halves2half2(h0, h1);
                *reinterpret_cast<__half2*>(p.ol + base1) = __halves2half2(l0, l1);
            }
        }
    }
}

// ============================================================================
// Softmax pieces
// ============================================================================
__global__ void colsum_kernel(const float* __restrict__ S, float* __restrict__ cs) {
    int b = blockIdx.y;
    int m = blockIdx.x * blockDim.x + threadIdx.x;
    const float* p = S + (size_t)b * NDIM * MEDIM + m;
    float s = 0.0f;
#pragma unroll 4
    for (int n = 0; n < NDIM; n++) s += expf(p[(size_t)n * MEDIM]);
    cs[b * MEDIM + m] = s;
}

// A = exp(S)/colsum (in place), plus 2-limb fp16 split of A
__global__ void softmax_split_kernel(float* __restrict__ S, const float* __restrict__ cs,
                                     hf* __restrict__ ah, hf* __restrict__ al) {
    size_t g = (size_t)blockIdx.x * blockDim.x + threadIdx.x;
    int b = (int)(g >> 20);
    int m = (int)(g & (MEDIM - 1));
    float v = expf(S[g]) / cs[b * MEDIM + m];
    S[g] = v;
    split2h(v, ah[g], al[g]);
}

// ============================================================================
// Host launch
// ============================================================================
extern "C" void kernel_launch(void* const* d_in, const int* in_sizes, int n_in,
                              void* d_out, int out_size) {
    const float* z = (const float*)d_in[0];
    const float* e = (const float*)d_in[1];
    const float* M = (const float*)d_in[2];

    float* e_out = (float*)d_out;
    float* A_out = (float*)d_out + (size_t)BATCH * NDIM * DDIM;

    hf *z1, *z2, *m1, *m2, *p1, *p2, *e1, *e2, *t1, *t2, *a1, *a2;
    float* cs;
    cudaGetSymbolAddress((void**)&z1, g_z1); cudaGetSymbolAddress((void**)&z2, g_z2);
    cudaGetSymbolAddress((void**)&m1, g_m1); cudaGetSymbolAddress((void**)&m2, g_m2);
    cudaGetSymbolAddress((void**)&p1, g_p1); cudaGetSymbolAddress((void**)&p2, g_p2);
    cudaGetSymbolAddress((void**)&e1, g_e1); cudaGetSymbolAddress((void**)&e2, g_e2);
    cudaGetSymbolAddress((void**)&t1, g_t1); cudaGetSymbolAddress((void**)&t2, g_t2);
    cudaGetSymbolAddress((void**)&a1, g_a1); cudaGetSymbolAddress((void**)&a2, g_a2);
    cudaGetSymbolAddress((void**)&cs, g_colsum);

    cudaFuncSetAttribute(mm_kernel<2>, cudaFuncAttributeMaxDynamicSharedMemorySize, SMEM_BYTES);
    cudaFuncSetAttribute(mm_kernel<1>, cudaFuncAttributeMaxDynamicSharedMemorySize, SMEM_BYTES);
    cudaFuncSetAttribute(mm_kernel<0>, cudaFuncAttributeMaxDynamicSharedMemorySize, SMEM_BYTES);

    const long S8 = (long)1024 * 1024;

    // ---- Prep: limb splits ----
    split2_kernel<<<(BATCH * S8) / 256, 256>>>(z, z1, z2);
    split2_kernel<<<(BATCH * S8) / 256, 256>>>(e, e1, e2);
    tsplit2_kernel<<<dim3(32, 32, 1), dim3(32, 8)>>>(M, m1, m2);
    tsplit2_kernel<<<dim3(32, 32, BATCH), dim3(32, 8)>>>(e, t1, t2);

    dim3 gg(8, 8, BATCH);   // cols/128, rows/128, batch
    dim3 gb(256);

    // ---- GEMM1: zM = z1*m1 + z1*m2 + z2*m1 -> zM fp16 limbs ----
    {
        GemmParams p{};
        p.a1 = z1; p.a2 = z2; p.b1 = m1; p.b2 = m2;
        p.strideA = S8; p.strideB = 0; p.strideC = S8;
        p.oh = p1; p.ol = p2; p.C = nullptr;
        mm_kernel<2><<<gg, gb, SMEM_BYTES>>>(p);
    }
    // ---- GEMM2: S = sigmoid(p1*e1 + p1*e2 + p2*e1) ----
    {
        GemmParams p{};
        p.a1 = p1; p.a2 = p2; p.b1 = e1; p.b2 = e2;
        p.strideA = S8; p.strideB = S8; p.strideC = S8;
        p.C = A_out;
        mm_kernel<1><<<gg, gb, SMEM_BYTES>>>(p);
    }
    // ---- Softmax over N (column axis) ----
    colsum_kernel<<<dim3(MEDIM / 256, BATCH), gb>>>(A_out, cs);
    softmax_split_kernel<<<(BATCH * S8) / 256, 256>>>(A_out, cs, a1, a2);

    // ---- GEMM3: e_out = a1*t1 + a1*t2 + a2*t1 ----
    {
        GemmParams p{};
        p.a1 = a1; p.a2 = a2; p.b1 = t1; p.b2 = t2;
        p.strideA = S8; p.strideB = S8; p.strideC = S8;
        p.C = e_out;
        mm_kernel<0><<<gg, gb, SMEM_BYTES>>>(p);
    }
}

// round 13
// speedup vs baseline: 2.5494x; 1.1792x over previous
#include <cuda_runtime.h>
#include <cuda_fp16.h>
#include <cstdint>
#include <math.h>

// Problem constants
#define BATCH 8
#define NDIM  1024
#define MEDIM 1024
#define DDIM  1024

typedef __half hf;

// ============================================================================
// Scratch (device globals; no allocation allowed)
// ============================================================================
#define EL8M ((size_t)BATCH * 1024 * 1024)
__device__ hf g_z1[EL8M], g_z2[EL8M];               // z limbs [B,N,D]
__device__ hf g_m1[1024*1024], g_m2[1024*1024];     // M^T limbs [D,D]
__device__ hf g_p1[EL8M], g_p2[EL8M];               // zM limbs [B,N,D]
__device__ hf g_e1[EL8M], g_e2[EL8M];               // e limbs [B,ME,D]
__device__ hf g_t1[EL8M];                           // e^T hi limb [B,D,ME]
__device__ hf g_a1[EL8M];                           // A hi limb [B,N,ME]
__device__ float g_colsum[BATCH * MEDIM];

// ============================================================================
// PTX helpers (compute_103-safe: mma.sync / ldmatrix / cp.async only)
// ============================================================================
__device__ __forceinline__ uint32_t smem_u32(const void* p) {
    uint32_t a;
    asm("{ .reg .u64 t; cvta.to.shared.u64 t, %1; cvt.u32.u64 %0, t; }" : "=r"(a) : "l"(p));
    return a;
}

#define CP_ASYNC16(dst, src) \
    asm volatile("cp.async.cg.shared.global [%0], [%1], 16;" :: "r"(dst), "l"(src))
#define CP_COMMIT() asm volatile("cp.async.commit_group;" ::: "memory")
#define CP_WAIT1()  asm volatile("cp.async.wait_group 1;" ::: "memory")

#define LDMATRIX_X4(r, addr) \
    asm volatile("ldmatrix.sync.aligned.m8n8.x4.shared.b16 {%0,%1,%2,%3}, [%4];" \
        : "=r"((r)[0]), "=r"((r)[1]), "=r"((r)[2]), "=r"((r)[3]) : "r"(addr))

#define MMA16816(d, a, b0, b1) \
    asm volatile("mma.sync.aligned.m16n8k16.row.col.f32.f16.f16.f32 " \
        "{%0,%1,%2,%3}, {%4,%5,%6,%7}, {%8,%9}, {%0,%1,%2,%3};" \
        : "+f"((d)[0]), "+f"((d)[1]), "+f"((d)[2]), "+f"((d)[3]) \
        : "r"((a)[0]), "r"((a)[1]), "r"((a)[2]), "r"((a)[3]), "r"(b0), "r"(b1))

// 64-byte-row swizzle (Swizzle<2,4,3>): bits[5:4] ^= bits[8:7]
#define SWZ64(x) ((x) ^ (((x) >> 3) & 0x30))

// ============================================================================
// Split helpers: fp32 -> 2 fp16 limbs (22 mantissa bits captured)
// ============================================================================
__device__ __forceinline__ void split2h(float v, hf& h, hf& l) {
    h = __float2half_rn(v);
    l = __float2half_rn(v - __half2float(h));
}

__global__ void split2_kernel(const float* __restrict__ x, hf* __restrict__ h,
                              hf* __restrict__ l) {
    size_t i = (size_t)blockIdx.x * blockDim.x + threadIdx.x;
    split2h(x[i], h[i], l[i]);
}

// batched transpose + 2-split: out[b][r][c] = in[b][c][r] (gridDim.z=1 for M)
__global__ void tsplit2_kernel(const float* __restrict__ x, hf* __restrict__ h,
                               hf* __restrict__ l) {
    __shared__ float tile[32][33];
    size_t boff = (size_t)blockIdx.z * 1024 * 1024;
    int x0 = blockIdx.x * 32, y0 = blockIdx.y * 32;
    for (int i = threadIdx.y; i < 32; i += 8)
        tile[i][threadIdx.x] = x[boff + (size_t)(y0 + i) * 1024 + x0 + threadIdx.x];
    __syncthreads();
    for (int i = threadIdx.y; i < 32; i += 8) {
        float v = tile[threadIdx.x][i];
        size_t o = boff + (size_t)(x0 + i) * 1024 + y0 + threadIdx.x;
        split2h(v, h[o], l[o]);
    }
}

// batched transpose + fp16 round (hi limb only): out[b][r][c] = fp16(in[b][c][r])
__global__ void tsplit1_kernel(const float* __restrict__ x, hf* __restrict__ h) {
    __shared__ float tile[32][33];
    size_t boff = (size_t)blockIdx.z * 1024 * 1024;
    int x0 = blockIdx.x * 32, y0 = blockIdx.y * 32;
    for (int i = threadIdx.y; i < 32; i += 8)
        tile[i][threadIdx.x] = x[boff + (size_t)(y0 + i) * 1024 + x0 + threadIdx.x];
    __syncthreads();
    for (int i = threadIdx.y; i < 32; i += 8) {
        float v = tile[threadIdx.x][i];
        size_t o = boff + (size_t)(x0 + i) * 1024 + y0 + threadIdx.x;
        h[o] = __float2half_rn(v);
    }
}

// ============================================================================
// fp16 GEMM (mma.sync m16n8k16), fp32 accum.
// NPAIR=3: C = a1@b1^T + a1@b2^T + a2@b1^T  (fused limb residency)
// NPAIR=1: C = a1@b1^T                      (plain fp16)
// CTA tile 128x128, warp tile 32x64 (8 warps, 4x2), BK=32, 3-stage cp.async,
// single barrier per chunk, 2 CTAs/SM.
// EPI: 0 = f32 store, 1 = sigmoid f32, 2 = 2-limb fp16 split.
// ============================================================================
struct GemmParams {
    const hf *a1, *a2, *b1, *b2;
    long strideA, strideB, strideC;
    float* C;
    hf *oh, *ol;
};

// Stage: NPAIR=3 -> A1|A2|B1|B2 8KB each = 32KB; NPAIR=1 -> A1|B1 = 16KB
template <int NPAIR>
struct StageCfg { static constexpr uint32_t bytes = (NPAIR == 3) ? 32768u : 16384u; };
#define SMEM_BYTES_3 98304
#define SMEM_BYTES_1 49152

template <int NPAIR, int EPI>
__global__ void __launch_bounds__(256, 2) mm_kernel(GemmParams p) {
    constexpr uint32_t STAGE = StageCfg<NPAIR>::bytes;
    constexpr uint32_t OFF_A2 = 8192u;                       // NPAIR=3 only
    constexpr uint32_t OFF_B1 = (NPAIR == 3) ? 16384u : 8192u;
    constexpr uint32_t OFF_B2 = 24576u;                      // NPAIR=3 only

    extern __shared__ char smem[];
    const uint32_t sb = smem_u32(smem);
    const int tid = threadIdx.x;
    const int lid = tid & 31;
    const int wid = tid >> 5;
    const int wm = wid & 3;    // 0..3 -> 32-row slice
    const int wn = wid >> 2;   // 0..1 -> 64-col slice

    const int b = blockIdx.z;
    const long row0 = (long)blockIdx.y * 128;
    const long col0 = (long)blockIdx.x * 128;

    const int NCH = 32;   // K chunks of 32

    float acc[2][8][4];
#pragma unroll
    for (int i = 0; i < 2; i++)
#pragma unroll
        for (int j = 0; j < 8; j++)
#pragma unroll
            for (int k = 0; k < 4; k++) acc[i][j][k] = 0.0f;

    // Per chunk: tiles of 128x32 fp16 = 8KB each (512 x16B transfers each).
    auto load_chunk = [&](int c, int stage) {
        const long kk = (long)c << 5;
        const uint32_t s0 = sb + (uint32_t)stage * STAGE;
        const hf* A1g = p.a1 + (long)b * p.strideA + kk;
        const hf* B1g = p.b1 + (long)b * p.strideB + kk;
        const hf* A2g = p.a2 ? p.a2 + (long)b * p.strideA + kk : nullptr;
        const hf* B2g = p.b2 ? p.b2 + (long)b * p.strideB + kk : nullptr;
#pragma unroll
        for (int t = 0; t < 2; t++) {
            int idx = tid + (t << 8);          // 0..511
            int r = idx >> 2;                  // 0..127
            int c16 = idx & 3;                 // 16B unit in 64B row
            uint32_t bo = SWZ64((uint32_t)(r << 6) + (uint32_t)(c16 << 4));
            long goA = (row0 + r) * 1024 + (c16 << 3);
            long goB = (col0 + r) * 1024 + (c16 << 3);
            CP_ASYNC16(s0 + bo,          A1g + goA);
            CP_ASYNC16(s0 + OFF_B1 + bo, B1g + goB);
            if (NPAIR == 3) {
                CP_ASYNC16(s0 + OFF_A2 + bo, A2g + goA);
                CP_ASYNC16(s0 + OFF_B2 + bo, B2g + goB);
            }
        }
    };

    load_chunk(0, 0); CP_COMMIT();
    load_chunk(1, 1); CP_COMMIT();

    for (int c = 0; c < NCH; c++) {
        CP_WAIT1();          // chunk c resident (only c+1 may be pending)
        __syncthreads();     // all warps: done with chunk c-1, see chunk c
        if (c + 2 < NCH) load_chunk(c + 2, (c + 2) % 3);
        CP_COMMIT();         // unconditional: keeps group accounting in tail

        const uint32_t s0 = sb + (uint32_t)(c % 3) * STAGE;

#pragma unroll
        for (int j = 0; j < 2; j++) {       // k16 step within 32-chunk
            uint32_t af[2][2][4];
#pragma unroll
            for (int mi = 0; mi < 2; mi++) {
                int row = wm * 32 + mi * 16 + (lid & 15);
                uint32_t bo = SWZ64((uint32_t)(row << 6) + (uint32_t)(j << 5)
                            + (uint32_t)((lid >> 4) << 4));
                LDMATRIX_X4(af[0][mi], s0 + bo);                          // a1
                if (NPAIR == 3) LDMATRIX_X4(af[1][mi], s0 + OFF_A2 + bo); // a2
            }
#pragma unroll
            for (int ni = 0; ni < 4; ni++) {  // 16-col groups
                int nr = wn * 64 + ni * 16 + (lid & 7) + (((lid >> 4) & 1) << 3);
                uint32_t bo = SWZ64((uint32_t)(nr << 6) + (uint32_t)(j << 5)
                            + (uint32_t)(((lid >> 3) & 1) << 4));
                uint32_t b1f[4];
                LDMATRIX_X4(b1f, s0 + OFF_B1 + bo);
#pragma unroll
                for (int mi = 0; mi < 2; mi++) {
                    MMA16816(acc[mi][ni * 2 + 0], af[0][mi], b1f[0], b1f[1]);
                    MMA16816(acc[mi][ni * 2 + 1], af[0][mi], b1f[2], b1f[3]);
                }
                if (NPAIR == 3) {
                    uint32_t b2f[4];
                    LDMATRIX_X4(b2f, s0 + OFF_B2 + bo);
#pragma unroll
                    for (int mi = 0; mi < 2; mi++) {
                        // a1*b2 (hl)
                        MMA16816(acc[mi][ni * 2 + 0], af[0][mi], b2f[0], b2f[1]);
                        MMA16816(acc[mi][ni * 2 + 1], af[0][mi], b2f[2], b2f[3]);
                        // a2*b1 (lh)
                        MMA16816(acc[mi][ni * 2 + 0], af[1][mi], b1f[0], b1f[1]);
                        MMA16816(acc[mi][ni * 2 + 1], af[1][mi], b1f[2], b1f[3]);
                    }
                }
            }
        }
    }

    // ---- Epilogue (direct from registers) ----
    const int r_in = lid >> 2;
    const int c_in = (lid & 3) << 1;
#pragma unroll
    for (int mi = 0; mi < 2; mi++) {
        const long row = row0 + wm * 32 + mi * 16 + r_in;
#pragma unroll
        for (int nj = 0; nj < 8; nj++) {
            const long colg = col0 + wn * 64 + nj * 8 + c_in;
            float v0 = acc[mi][nj][0], v1 = acc[mi][nj][1];
            float v2 = acc[mi][nj][2], v3 = acc[mi][nj][3];
            if (EPI == 0 || EPI == 1) {
                if (EPI == 1) {
                    v0 = 1.0f / (1.0f + expf(-v0));
                    v1 = 1.0f / (1.0f + expf(-v1));
                    v2 = 1.0f / (1.0f + expf(-v2));
                    v3 = 1.0f / (1.0f + expf(-v3));
                }
                float* Cp = p.C + (long)b * p.strideC;
                *reinterpret_cast<float2*>(Cp + row * 1024 + colg)       = make_float2(v0, v1);
                *reinterpret_cast<float2*>(Cp + (row + 8) * 1024 + colg) = make_float2(v2, v3);
            } else {
                const long base0 = (long)b * p.strideC + row * 1024 + colg;
                const long base1 = base0 + 8 * 1024;
                hf h0, l0, h1, l1;
                split2h(v0, h0, l0); split2h(v1, h1, l1);
                *reinterpret_cast<__half2*>(p.oh + base0) = __halves2half2(h0, h1);
                *reinterpret_cast<__half2*>(p.ol + base0) = __halves2half2(l0, l1);
                split2h(v2, h0, l0); split2h(v3, h1, l1);
                *reinterpret_cast<__half2*>(p.oh + base1) = __halves2half2(h0, h1);
                *reinterpret_cast<__half2*>(p.ol + base1) = __halves2half2(l0, l1);
            }
        }
    }
}

// ============================================================================
// Softmax pieces
// ============================================================================
__global__ void colsum_kernel(const float* __restrict__ S, float* __restrict__ cs) {
    int b = blockIdx.y;
    int m = blockIdx.x * blockDim.x + threadIdx.x;
    const float* p = S + (size_t)b * NDIM * MEDIM + m;
    float s = 0.0f;
#pragma unroll 4
    for (int n = 0; n < NDIM; n++) s += expf(p[(size_t)n * MEDIM]);
    cs[b * MEDIM + m] = s;
}

// A = exp(S)/colsum (in place), plus fp16 round of A (hi limb only)
__global__ void softmax_split_kernel(float* __restrict__ S, const float* __restrict__ cs,
                                     hf* __restrict__ ah) {
    size_t g = (size_t)blockIdx.x * blockDim.x + threadIdx.x;
    int b = (int)(g >> 20);
    int m = (int)(g & (MEDIM - 1));
    float v = expf(S[g]) / cs[b * MEDIM + m];
    S[g] = v;
    ah[g] = __float2half_rn(v);
}

// ============================================================================
// Host launch
// ============================================================================
extern "C" void kernel_launch(void* const* d_in, const int* in_sizes, int n_in,
                              void* d_out, int out_size) {
    const float* z = (const float*)d_in[0];
    const float* e = (const float*)d_in[1];
    const float* M = (const float*)d_in[2];

    float* e_out = (float*)d_out;
    float* A_out = (float*)d_out + (size_t)BATCH * NDIM * DDIM;

    hf *z1, *z2, *m1, *m2, *p1, *p2, *e1, *e2, *t1, *a1;
    float* cs;
    cudaGetSymbolAddress((void**)&z1, g_z1); cudaGetSymbolAddress((void**)&z2, g_z2);
    cudaGetSymbolAddress((void**)&m1, g_m1); cudaGetSymbolAddress((void**)&m2, g_m2);
    cudaGetSymbolAddress((void**)&p1, g_p1); cudaGetSymbolAddress((void**)&p2, g_p2);
    cudaGetSymbolAddress((void**)&e1, g_e1); cudaGetSymbolAddress((void**)&e2, g_e2);
    cudaGetSymbolAddress((void**)&t1, g_t1);
    cudaGetSymbolAddress((void**)&a1, g_a1);
    cudaGetSymbolAddress((void**)&cs, g_colsum);

    cudaFuncSetAttribute(mm_kernel<3, 2>, cudaFuncAttributeMaxDynamicSharedMemorySize, SMEM_BYTES_3);
    cudaFuncSetAttribute(mm_kernel<3, 1>, cudaFuncAttributeMaxDynamicSharedMemorySize, SMEM_BYTES_3);
    cudaFuncSetAttribute(mm_kernel<1, 0>, cudaFuncAttributeMaxDynamicSharedMemorySize, SMEM_BYTES_1);

    const long S8 = (long)1024 * 1024;

    // ---- Prep: limb splits ----
    split2_kernel<<<(BATCH * S8) / 256, 256>>>(z, z1, z2);
    split2_kernel<<<(BATCH * S8) / 256, 256>>>(e, e1, e2);
    tsplit2_kernel<<<dim3(32, 32, 1), dim3(32, 8)>>>(M, m1, m2);
    tsplit1_kernel<<<dim3(32, 32, BATCH), dim3(32, 8)>>>(e, t1);

    dim3 gg(8, 8, BATCH);   // cols/128, rows/128, batch
    dim3 gb(256);

    // ---- GEMM1: zM = z1*m1 + z1*m2 + z2*m1 -> zM fp16 limbs ----
    {
        GemmParams p{};
        p.a1 = z1; p.a2 = z2; p.b1 = m1; p.b2 = m2;
        p.strideA = S8; p.strideB = 0; p.strideC = S8;
        p.oh = p1; p.ol = p2; p.C = nullptr;
        mm_kernel<3, 2><<<gg, gb, SMEM_BYTES_3>>>(p);
    }
    // ---- GEMM2: S = sigmoid(p1*e1 + p1*e2 + p2*e1) ----
    {
        GemmParams p{};
        p.a1 = p1; p.a2 = p2; p.b1 = e1; p.b2 = e2;
        p.strideA = S8; p.strideB = S8; p.strideC = S8;
        p.C = A_out;
        mm_kernel<3, 1><<<gg, gb, SMEM_BYTES_3>>>(p);
    }
    // ---- Softmax over N (column axis) ----
    colsum_kernel<<<dim3(MEDIM / 256, BATCH), gb>>>(A_out, cs);
    softmax_split_kernel<<<(BATCH * S8) / 256, 256>>>(A_out, cs, a1);

    // ---- GEMM3: e_out = a1 @ t1^T  (plain fp16, fp32 accum) ----
    {
        GemmParams p{};
        p.a1 = a1; p.a2 = nullptr; p.b1 = t1; p.b2 = nullptr;
        p.strideA = S8; p.strideB = S8; p.strideC = S8;
        p.C = e_out;
        mm_kernel<1, 0><<<gg, gb, SMEM_BYTES_1>>>(p);
    }
}

// round 17
// speedup vs baseline: 3.4129x; 1.3387x over previous
#include <cuda_runtime.h>
#include <cuda_fp16.h>
#include <cstdint>
#include <math.h>

// Problem constants
#define BATCH 8
#define NDIM  1024
#define MEDIM 1024
#define DDIM  1024

typedef __half hf;

// ============================================================================
// Scratch (device globals; no allocation allowed)
// ============================================================================
#define EL8M ((size_t)BATCH * 1024 * 1024)
__device__ hf g_z1[EL8M], g_z2[EL8M];               // z limbs [B,N,D]
__device__ hf g_m1[1024*1024], g_m2[1024*1024];     // M^T limbs [D,D]
__device__ hf g_p1[EL8M], g_p2[EL8M];               // zM limbs [B,N,D]
__device__ hf g_e1[EL8M], g_e2[EL8M];               // e limbs [B,ME,D]
__device__ hf g_t1[EL8M];                           // e^T hi limb [B,D,ME]
__device__ hf g_a1[EL8M];                           // A hi limb [B,N,ME]
__device__ float g_colsum[BATCH * MEDIM];

// ============================================================================
// PTX helpers (compute_103-safe: mma.sync / ldmatrix / cp.async only)
// ============================================================================
__device__ __forceinline__ uint32_t smem_u32(const void* p) {
    uint32_t a;
    asm("{ .reg .u64 t; cvta.to.shared.u64 t, %1; cvt.u32.u64 %0, t; }" : "=r"(a) : "l"(p));
    return a;
}

#define CP_ASYNC16(dst, src) \
    asm volatile("cp.async.cg.shared.global [%0], [%1], 16;" :: "r"(dst), "l"(src))
#define CP_COMMIT() asm volatile("cp.async.commit_group;" ::: "memory")
#define CP_WAIT1()  asm volatile("cp.async.wait_group 1;" ::: "memory")

#define LDMATRIX_X4(r, addr) \
    asm volatile("ldmatrix.sync.aligned.m8n8.x4.shared.b16 {%0,%1,%2,%3}, [%4];" \
        : "=r"((r)[0]), "=r"((r)[1]), "=r"((r)[2]), "=r"((r)[3]) : "r"(addr))

#define MMA16816(d, a, b0, b1) \
    asm volatile("mma.sync.aligned.m16n8k16.row.col.f32.f16.f16.f32 " \
        "{%0,%1,%2,%3}, {%4,%5,%6,%7}, {%8,%9}, {%0,%1,%2,%3};" \
        : "+f"((d)[0]), "+f"((d)[1]), "+f"((d)[2]), "+f"((d)[3]) \
        : "r"((a)[0]), "r"((a)[1]), "r"((a)[2]), "r"((a)[3]), "r"(b0), "r"(b1))

// 64-byte-row swizzle (Swizzle<2,4,3>): bits[5:4] ^= bits[8:7]
#define SWZ64(x) ((x) ^ (((x) >> 3) & 0x30))

// ============================================================================
// Split helpers: fp32 -> 2 fp16 limbs (22 mantissa bits captured)
// ============================================================================
__device__ __forceinline__ void split2h(float v, hf& h, hf& l) {
    h = __float2half_rn(v);
    l = __float2half_rn(v - __half2float(h));
}

// vectorized elementwise 2-split: 4 floats / thread
__global__ void split2_kernel(const float4* __restrict__ x, __half2* __restrict__ h,
                              __half2* __restrict__ l) {
    size_t i = (size_t)blockIdx.x * blockDim.x + threadIdx.x;
    float4 v = x[i];
    hf h0, l0, h1, l1, h2, l2, h3, l3;
    split2h(v.x, h0, l0); split2h(v.y, h1, l1);
    split2h(v.z, h2, l2); split2h(v.w, h3, l3);
    h[2 * i]     = __halves2half2(h0, h1);
    h[2 * i + 1] = __halves2half2(h2, h3);
    l[2 * i]     = __halves2half2(l0, l1);
    l[2 * i + 1] = __halves2half2(l2, l3);
}

// batched transpose + 2-split: out[b][r][c] = in[b][c][r] (gridDim.z=1 for M)
__global__ void tsplit2_kernel(const float* __restrict__ x, hf* __restrict__ h,
                               hf* __restrict__ l) {
    __shared__ float tile[32][33];
    size_t boff = (size_t)blockIdx.z * 1024 * 1024;
    int x0 = blockIdx.x * 32, y0 = blockIdx.y * 32;
    for (int i = threadIdx.y; i < 32; i += 8)
        tile[i][threadIdx.x] = x[boff + (size_t)(y0 + i) * 1024 + x0 + threadIdx.x];
    __syncthreads();
    for (int i = threadIdx.y; i < 32; i += 8) {
        float v = tile[threadIdx.x][i];
        size_t o = boff + (size_t)(x0 + i) * 1024 + y0 + threadIdx.x;
        split2h(v, h[o], l[o]);
    }
}

// batched transpose + fp16 round (hi limb only): out[b][r][c] = fp16(in[b][c][r])
__global__ void tsplit1_kernel(const float* __restrict__ x, hf* __restrict__ h) {
    __shared__ float tile[32][33];
    size_t boff = (size_t)blockIdx.z * 1024 * 1024;
    int x0 = blockIdx.x * 32, y0 = blockIdx.y * 32;
    for (int i = threadIdx.y; i < 32; i += 8)
        tile[i][threadIdx.x] = x[boff + (size_t)(y0 + i) * 1024 + x0 + threadIdx.x];
    __syncthreads();
    for (int i = threadIdx.y; i < 32; i += 8) {
        float v = tile[threadIdx.x][i];
        size_t o = boff + (size_t)(x0 + i) * 1024 + y0 + threadIdx.x;
        h[o] = __float2half_rn(v);
    }
}

__global__ void zero_kernel(float* __restrict__ p) {
    p[blockIdx.x * 256 + threadIdx.x] = 0.0f;
}

// ============================================================================
// fp16 GEMM (mma.sync m16n8k16), fp32 accum.
// NPAIR=3: C = a1@b1^T + a1@b2^T + a2@b1^T  (fused limb residency)
// NPAIR=1: C = a1@b1^T                      (plain fp16)
// CTA tile 128x128, warp tile 32x64 (8 warps, 4x2), BK=32, 3-stage cp.async,
// single barrier per chunk, 2 CTAs/SM.
// EPI: 0 = f32 store, 1 = sigmoid f32 + fused exp-colsum atomics,
//      2 = 2-limb fp16 split.
// ============================================================================
struct GemmParams {
    const hf *a1, *a2, *b1, *b2;
    long strideA, strideB, strideC;
    float* C;
    hf *oh, *ol;
    float* cs;   // colsum (EPI==1)
};

// Stage: NPAIR=3 -> A1|A2|B1|B2 8KB each = 32KB; NPAIR=1 -> A1|B1 = 16KB
template <int NPAIR>
struct StageCfg { static constexpr uint32_t bytes = (NPAIR == 3) ? 32768u : 16384u; };
#define SMEM_BYTES_3 98304
#define SMEM_BYTES_1 49152

template <int NPAIR, int EPI>
__global__ void __launch_bounds__(256, 2) mm_kernel(GemmParams p) {
    constexpr uint32_t STAGE = StageCfg<NPAIR>::bytes;
    constexpr uint32_t OFF_A2 = 8192u;                       // NPAIR=3 only
    constexpr uint32_t OFF_B1 = (NPAIR == 3) ? 16384u : 8192u;
    constexpr uint32_t OFF_B2 = 24576u;                      // NPAIR=3 only

    extern __shared__ char smem[];
    const uint32_t sb = smem_u32(smem);
    const int tid = threadIdx.x;
    const int lid = tid & 31;
    const int wid = tid >> 5;
    const int wm = wid & 3;    // 0..3 -> 32-row slice
    const int wn = wid >> 2;   // 0..1 -> 64-col slice

    const int b = blockIdx.z;
    const long row0 = (long)blockIdx.y * 128;
    const long col0 = (long)blockIdx.x * 128;

    const int NCH = 32;   // K chunks of 32

    float acc[2][8][4];
#pragma unroll
    for (int i = 0; i < 2; i++)
#pragma unroll
        for (int j = 0; j < 8; j++)
#pragma unroll
            for (int k = 0; k < 4; k++) acc[i][j][k] = 0.0f;

    // Per chunk: tiles of 128x32 fp16 = 8KB each (512 x16B transfers each).
    auto load_chunk = [&](int c, int stage) {
        const long kk = (long)c << 5;
        const uint32_t s0 = sb + (uint32_t)stage * STAGE;
        const hf* A1g = p.a1 + (long)b * p.strideA + kk;
        const hf* B1g = p.b1 + (long)b * p.strideB + kk;
        const hf* A2g = p.a2 ? p.a2 + (long)b * p.strideA + kk : nullptr;
        const hf* B2g = p.b2 ? p.b2 + (long)b * p.strideB + kk : nullptr;
#pragma unroll
        for (int t = 0; t < 2; t++) {
            int idx = tid + (t << 8);          // 0..511
            int r = idx >> 2;                  // 0..127
            int c16 = idx & 3;                 // 16B unit in 64B row
            uint32_t bo = SWZ64((uint32_t)(r << 6) + (uint32_t)(c16 << 4));
            long goA = (row0 + r) * 1024 + (c16 << 3);
            long goB = (col0 + r) * 1024 + (c16 << 3);
            CP_ASYNC16(s0 + bo,          A1g + goA);
            CP_ASYNC16(s0 + OFF_B1 + bo, B1g + goB);
            if (NPAIR == 3) {
                CP_ASYNC16(s0 + OFF_A2 + bo, A2g + goA);
                CP_ASYNC16(s0 + OFF_B2 + bo, B2g + goB);
            }
        }
    };

    load_chunk(0, 0); CP_COMMIT();
    load_chunk(1, 1); CP_COMMIT();

    for (int c = 0; c < NCH; c++) {
        CP_WAIT1();          // chunk c resident (only c+1 may be pending)
        __syncthreads();     // all warps: done with chunk c-1, see chunk c
        if (c + 2 < NCH) load_chunk(c + 2, (c + 2) % 3);
        CP_COMMIT();         // unconditional: keeps group accounting in tail

        const uint32_t s0 = sb + (uint32_t)(c % 3) * STAGE;

#pragma unroll
        for (int j = 0; j < 2; j++) {       // k16 step within 32-chunk
            uint32_t af[2][2][4];
#pragma unroll
            for (int mi = 0; mi < 2; mi++) {
                int row = wm * 32 + mi * 16 + (lid & 15);
                uint32_t bo = SWZ64((uint32_t)(row << 6) + (uint32_t)(j << 5)
                            + (uint32_t)((lid >> 4) << 4));
                LDMATRIX_X4(af[0][mi], s0 + bo);                          // a1
                if (NPAIR == 3) LDMATRIX_X4(af[1][mi], s0 + OFF_A2 + bo); // a2
            }
#pragma unroll
            for (int ni = 0; ni < 4; ni++) {  // 16-col groups
                int nr = wn * 64 + ni * 16 + (lid & 7) + (((lid >> 4) & 1) << 3);
                uint32_t bo = SWZ64((uint32_t)(nr << 6) + (uint32_t)(j << 5)
                            + (uint32_t)(((lid >> 3) & 1) << 4));
                uint32_t b1f[4];
                LDMATRIX_X4(b1f, s0 + OFF_B1 + bo);
#pragma unroll
                for (int mi = 0; mi < 2; mi++) {
                    MMA16816(acc[mi][ni * 2 + 0], af[0][mi], b1f[0], b1f[1]);
                    MMA16816(acc[mi][ni * 2 + 1], af[0][mi], b1f[2], b1f[3]);
                }
                if (NPAIR == 3) {
                    uint32_t b2f[4];
                    LDMATRIX_X4(b2f, s0 + OFF_B2 + bo);
#pragma unroll
                    for (int mi = 0; mi < 2; mi++) {
                        // a1*b2 (hl)
                        MMA16816(acc[mi][ni * 2 + 0], af[0][mi], b2f[0], b2f[1]);
                        MMA16816(acc[mi][ni * 2 + 1], af[0][mi], b2f[2], b2f[3]);
                        // a2*b1 (lh)
                        MMA16816(acc[mi][ni * 2 + 0], af[1][mi], b1f[0], b1f[1]);
                        MMA16816(acc[mi][ni * 2 + 1], af[1][mi], b1f[2], b1f[3]);
                    }
                }
            }
        }
    }

    // ---- Epilogue (direct from registers) ----
    const int r_in = lid >> 2;
    const int c_in = (lid & 3) << 1;
    if (EPI == 1) {
        // sigmoid store + fused exp-colsum (softmax over rows/N axis)
        float* Cp = p.C + (long)b * p.strideC;
#pragma unroll
        for (int nj = 0; nj < 8; nj++) {
            const long colg = col0 + wn * 64 + nj * 8 + c_in;
            float c0 = 0.0f, c1 = 0.0f;
#pragma unroll
            for (int mi = 0; mi < 2; mi++) {
                const long row = row0 + wm * 32 + mi * 16 + r_in;
                float v0 = 1.0f / (1.0f + expf(-acc[mi][nj][0]));
                float v1 = 1.0f / (1.0f + expf(-acc[mi][nj][1]));
                float v2 = 1.0f / (1.0f + expf(-acc[mi][nj][2]));
                float v3 = 1.0f / (1.0f + expf(-acc[mi][nj][3]));
                *reinterpret_cast<float2*>(Cp + row * 1024 + colg)       = make_float2(v0, v1);
                *reinterpret_cast<float2*>(Cp + (row + 8) * 1024 + colg) = make_float2(v2, v3);
                c0 += expf(v0) + expf(v2);
                c1 += expf(v1) + expf(v3);
            }
            // reduce over the 8 lanes sharing this column pair (lid mod 4)
            c0 += __shfl_xor_sync(0xffffffff, c0, 4);
            c0 += __shfl_xor_sync(0xffffffff, c0, 8);
            c0 += __shfl_xor_sync(0xffffffff, c0, 16);
            c1 += __shfl_xor_sync(0xffffffff, c1, 4);
            c1 += __shfl_xor_sync(0xffffffff, c1, 8);
            c1 += __shfl_xor_sync(0xffffffff, c1, 16);
            if (lid < 4) {
                atomicAdd(p.cs + b * MEDIM + colg,     c0);
                atomicAdd(p.cs + b * MEDIM + colg + 1, c1);
            }
        }
    } else {
#pragma unroll
        for (int mi = 0; mi < 2; mi++) {
            const long row = row0 + wm * 32 + mi * 16 + r_in;
#pragma unroll
            for (int nj = 0; nj < 8; nj++) {
                const long colg = col0 + wn * 64 + nj * 8 + c_in;
                float v0 = acc[mi][nj][0], v1 = acc[mi][nj][1];
                float v2 = acc[mi][nj][2], v3 = acc[mi][nj][3];
                if (EPI == 0) {
                    float* Cp = p.C + (long)b * p.strideC;
                    *reinterpret_cast<float2*>(Cp + row * 1024 + colg)       = make_float2(v0, v1);
                    *reinterpret_cast<float2*>(Cp + (row + 8) * 1024 + colg) = make_float2(v2, v3);
                } else {
                    const long base0 = (long)b * p.strideC + row * 1024 + colg;
                    const long base1 = base0 + 8 * 1024;
                    hf h0, l0, h1, l1;
                    split2h(v0, h0, l0); split2h(v1, h1, l1);
                    *reinterpret_cast<__half2*>(p.oh + base0) = __halves2half2(h0, h1);
                    *reinterpret_cast<__half2*>(p.ol + base0) = __halves2half2(l0, l1);
                    split2h(v2, h0, l0); split2h(v3, h1, l1);
                    *reinterpret_cast<__half2*>(p.oh + base1) = __halves2half2(h0, h1);
                    *reinterpret_cast<__half2*>(p.ol + base1) = __halves2half2(l0, l1);
                }
            }
        }
    }
}

// ============================================================================
// Softmax finalize: A = exp(S)/colsum (in place), plus fp16 round of A.
// Vectorized: 4 elements / thread.
// ============================================================================
__global__ void softmax_split_kernel(float4* __restrict__ S, const float* __restrict__ cs,
                                     __half2* __restrict__ ah) {
    size_t i = (size_t)blockIdx.x * blockDim.x + threadIdx.x;  // float4 index
    size_t g = i << 2;                                         // element index
    int b = (int)(g >> 20);
    int m = (int)(g & (MEDIM - 1));
    const float* c = cs + b * MEDIM + m;
    float4 v = S[i];
    v.x = expf(v.x) / c[0];
    v.y = expf(v.y) / c[1];
    v.z = expf(v.z) / c[2];
    v.w = expf(v.w) / c[3];
    S[i] = v;
    ah[2 * i]     = __halves2half2(__float2half_rn(v.x), __float2half_rn(v.y));
    ah[2 * i + 1] = __halves2half2(__float2half_rn(v.z), __float2half_rn(v.w));
}

// ============================================================================
// Host launch
// ============================================================================
extern "C" void kernel_launch(void* const* d_in, const int* in_sizes, int n_in,
                              void* d_out, int out_size) {
    const float* z = (const float*)d_in[0];
    const float* e = (const float*)d_in[1];
    const float* M = (const float*)d_in[2];

    float* e_out = (float*)d_out;
    float* A_out = (float*)d_out + (size_t)BATCH * NDIM * DDIM;

    hf *z1, *z2, *m1, *m2, *p1, *p2, *e1, *e2, *t1, *a1;
    float* cs;
    cudaGetSymbolAddress((void**)&z1, g_z1); cudaGetSymbolAddress((void**)&z2, g_z2);
    cudaGetSymbolAddress((void**)&m1, g_m1); cudaGetSymbolAddress((void**)&m2, g_m2);
    cudaGetSymbolAddress((void**)&p1, g_p1); cudaGetSymbolAddress((void**)&p2, g_p2);
    cudaGetSymbolAddress((void**)&e1, g_e1); cudaGetSymbolAddress((void**)&e2, g_e2);
    cudaGetSymbolAddress((void**)&t1, g_t1);
    cudaGetSymbolAddress((void**)&a1, g_a1);
    cudaGetSymbolAddress((void**)&cs, g_colsum);

    cudaFuncSetAttribute(mm_kernel<3, 2>, cudaFuncAttributeMaxDynamicSharedMemorySize, SMEM_BYTES_3);
    cudaFuncSetAttribute(mm_kernel<3, 1>, cudaFuncAttributeMaxDynamicSharedMemorySize, SMEM_BYTES_3);
    cudaFuncSetAttribute(mm_kernel<1, 0>, cudaFuncAttributeMaxDynamicSharedMemorySize, SMEM_BYTES_1);

    const long S8 = (long)1024 * 1024;

    // ---- Prep: limb splits (vectorized) + colsum zero ----
    split2_kernel<<<(BATCH * S8) / 1024, 256>>>(
        (const float4*)z, (__half2*)z1, (__half2*)z2);
    split2_kernel<<<(BATCH * S8) / 1024, 256>>>(
        (const float4*)e, (__half2*)e1, (__half2*)e2);
    tsplit2_kernel<<<dim3(32, 32, 1), dim3(32, 8)>>>(M, m1, m2);
    tsplit1_kernel<<<dim3(32, 32, BATCH), dim3(32, 8)>>>(e, t1);
    zero_kernel<<<(BATCH * MEDIM) / 256, 256>>>(cs);

    dim3 gg(8, 8, BATCH);   // cols/128, rows/128, batch
    dim3 gb(256);

    // ---- GEMM1: zM = z1*m1 + z1*m2 + z2*m1 -> zM fp16 limbs ----
    {
        GemmParams p{};
        p.a1 = z1; p.a2 = z2; p.b1 = m1; p.b2 = m2;
        p.strideA = S8; p.strideB = 0; p.strideC = S8;
        p.oh = p1; p.ol = p2; p.C = nullptr;
        mm_kernel<3, 2><<<gg, gb, SMEM_BYTES_3>>>(p);
    }
    // ---- GEMM2: S = sigmoid(p1*e1 + p1*e2 + p2*e1), fused exp-colsum ----
    {
        GemmParams p{};
        p.a1 = p1; p.a2 = p2; p.b1 = e1; p.b2 = e2;
        p.strideA = S8; p.strideB = S8; p.strideC = S8;
        p.C = A_out; p.cs = cs;
        mm_kernel<3, 1><<<gg, gb, SMEM_BYTES_3>>>(p);
    }
    // ---- Softmax finalize over N (column axis) ----
    softmax_split_kernel<<<(BATCH * S8) / 1024, 256>>>(
        (float4*)A_out, cs, (__half2*)a1);

    // ---- GEMM3: e_out = a1 @ t1^T  (plain fp16, fp32 accum) ----
    {
        GemmParams p{};
        p.a1 = a1; p.a2 = nullptr; p.b1 = t1; p.b2 = nullptr;
        p.strideA = S8; p.strideB = S8; p.strideC = S8;
        p.C = e_out;
        mm_kernel<1, 0><<<gg, gb, SMEM_BYTES_1>>>(p);
    }
}